// round 1
// baseline (speedup 1.0000x reference)
#include <cuda_runtime.h>
#include <math.h>

// Problem constants
#define B_  2
#define S_  2048
#define HID_ 2048
#define NH_  32
#define NKV_ 8
#define HD_  64
#define GROUP_ 4

// Scratch (no cudaMalloc allowed)
__device__ float g_Q[(size_t)B_ * S_ * HID_];        // [b*S+s][h*64+d]
__device__ float g_K[(size_t)B_ * S_ * NKV_ * HD_];  // [b*S+s][kvh*64+d]
__device__ float g_V[(size_t)B_ * S_ * NKV_ * HD_];
__device__ float g_ctx[(size_t)B_ * S_ * HID_];

// ---------------------------------------------------------------------------
// GEMM: C[m][n] = sum_k A[m][k] * Bmat[n][k]   (both K-major, NT gemm)
// BM=BN=64, BK=16, 16x16 threads, 4x4 per thread
// ---------------------------------------------------------------------------
#define GBM 64
#define GBN 64
#define GBK 16
__global__ void __launch_bounds__(256) gemm_nt_kernel(
    const float* __restrict__ A, const float* __restrict__ Bm,
    float* __restrict__ C, int M, int N, int K)
{
    __shared__ float As[GBK][GBM + 1];
    __shared__ float Bs[GBK][GBN + 1];

    const int tid = threadIdx.y * 16 + threadIdx.x;
    const int m0 = blockIdx.y * GBM;
    const int n0 = blockIdx.x * GBN;

    float acc[4][4];
#pragma unroll
    for (int i = 0; i < 4; i++)
#pragma unroll
        for (int j = 0; j < 4; j++) acc[i][j] = 0.f;

    for (int k0 = 0; k0 < K; k0 += GBK) {
#pragma unroll
        for (int i = 0; i < 4; i++) {
            int idx = tid + i * 256;            // 0..1023
            int ml = idx / GBK, kl = idx % GBK; // coalesced along k
            As[kl][ml] = A[(size_t)(m0 + ml) * K + k0 + kl];
        }
#pragma unroll
        for (int i = 0; i < 4; i++) {
            int idx = tid + i * 256;
            int nl = idx / GBK, kl = idx % GBK;
            Bs[kl][nl] = Bm[(size_t)(n0 + nl) * K + k0 + kl];
        }
        __syncthreads();
#pragma unroll
        for (int kk = 0; kk < GBK; kk++) {
            float ra[4], rb[4];
#pragma unroll
            for (int i = 0; i < 4; i++) ra[i] = As[kk][threadIdx.y * 4 + i];
#pragma unroll
            for (int j = 0; j < 4; j++) rb[j] = Bs[kk][threadIdx.x * 4 + j];
#pragma unroll
            for (int i = 0; i < 4; i++)
#pragma unroll
                for (int j = 0; j < 4; j++) acc[i][j] += ra[i] * rb[j];
        }
        __syncthreads();
    }
#pragma unroll
    for (int i = 0; i < 4; i++)
#pragma unroll
        for (int j = 0; j < 4; j++)
            C[(size_t)(m0 + threadIdx.y * 4 + i) * N + n0 + threadIdx.x * 4 + j] = acc[i][j];
}

// ---------------------------------------------------------------------------
// RoPE, in place. X layout: [b*S+s][h*HD + d], nheads heads.
// One block = one (bs, h), 32 threads; thread i handles dims i and i+32.
// fp64 angle + sincos so rotation error is negligible vs 1e-3 budget.
// ---------------------------------------------------------------------------
__global__ void rope_kernel(float* __restrict__ X, int nheads)
{
    const int blk = blockIdx.x;
    const int h  = blk % nheads;
    const int bs = blk / nheads;          // b*S + s
    const int s  = bs % S_;
    const int i  = threadIdx.x;           // 0..31

    double inv_freq = exp(-(double)i / 32.0 * log(10000.0));
    double ang = (double)s * inv_freq;
    double cd, sd;
    sincos(ang, &sd, &cd);
    float c = (float)cd, sn = (float)sd;

    float* p = X + (size_t)bs * nheads * HD_ + (size_t)h * HD_;
    float x1 = p[i];
    float x2 = p[i + 32];
    p[i]      = x1 * c - x2 * sn;
    p[i + 32] = x2 * c + x1 * sn;
}

// ---------------------------------------------------------------------------
// Flash attention (fp32, causal). grid = (S/64, NH, B), block = 256.
// BM=64 query rows, BN=32 key cols per tile. Each thread: row r=tid/4,
// owns 8 score cols and 16 output dims. Online softmax.
// ---------------------------------------------------------------------------
#define FAM 64
#define FAN 32
__global__ void __launch_bounds__(256) flash_attn_kernel(
    const float* __restrict__ Q, const float* __restrict__ K,
    const float* __restrict__ V, float* __restrict__ O)
{
    __shared__ float Qs[FAM][HD_ + 1];
    __shared__ float Ks[FAN][HD_ + 1];
    __shared__ float Vs[FAN][HD_ + 1];
    __shared__ float Ss[FAM][FAN + 1];
    __shared__ float m_s[FAM], l_s[FAM];
    __shared__ float red1[FAM][4], red2[FAM][4];

    const int tid = threadIdx.x;
    const int b = blockIdx.z, h = blockIdx.y, qt = blockIdx.x;
    const int kvh = h / GROUP_;
    const int r  = tid >> 2;        // 0..63
    const int q4 = tid & 3;
    const int c0 = q4 * 8;
    const int d0 = q4 * 16;
    const float scale = 0.125f;     // 1/sqrt(64)

    const float* Qbase = Q + ((size_t)(b * S_ + qt * FAM)) * HID_ + h * HD_;
    const float* Kbase = K + (size_t)b * S_ * (NKV_ * HD_) + kvh * HD_;
    const float* Vbase = V + (size_t)b * S_ * (NKV_ * HD_) + kvh * HD_;

#pragma unroll
    for (int i = 0; i < 16; i++) {
        int idx = tid + i * 256;        // 0..4095
        int rr = idx >> 6, cc = idx & 63;
        Qs[rr][cc] = Qbase[(size_t)rr * HID_ + cc];
    }
    if (tid < FAM) { m_s[tid] = -INFINITY; l_s[tid] = 0.f; }

    float o_acc[16];
#pragma unroll
    for (int i = 0; i < 16; i++) o_acc[i] = 0.f;
    __syncthreads();

    const int ntiles = 2 * qt + 2;   // causal: cover cols up to qt*64+63
    for (int kt = 0; kt < ntiles; kt++) {
        // load K,V tiles 32x64
#pragma unroll
        for (int i = 0; i < 8; i++) {
            int idx = tid + i * 256;    // 0..2047
            int rr = idx >> 6, cc = idx & 63;
            size_t goff = ((size_t)(kt * FAN + rr)) * (NKV_ * HD_) + cc;
            Ks[rr][cc] = Kbase[goff];
            Vs[rr][cc] = Vbase[goff];
        }
        __syncthreads();

        // S = scale * Q K^T (this thread: row r, cols c0..c0+7)
        float sacc[8];
#pragma unroll
        for (int j = 0; j < 8; j++) sacc[j] = 0.f;
#pragma unroll
        for (int k = 0; k < HD_; k++) {
            float qv = Qs[r][k];
#pragma unroll
            for (int j = 0; j < 8; j++) sacc[j] += qv * Ks[c0 + j][k];
        }
        const int grow = qt * FAM + r;
        float mx = -INFINITY;
#pragma unroll
        for (int j = 0; j < 8; j++) {
            int gcol = kt * FAN + c0 + j;
            float s = (gcol <= grow) ? sacc[j] * scale : -INFINITY;
            sacc[j] = s;
            mx = fmaxf(mx, s);
        }
        red1[r][q4] = mx;
        __syncthreads();

        float m_old = m_s[r];
        float m_new = fmaxf(m_old,
            fmaxf(fmaxf(red1[r][0], red1[r][1]), fmaxf(red1[r][2], red1[r][3])));
        float psum = 0.f;
#pragma unroll
        for (int j = 0; j < 8; j++) {
            float p = __expf(sacc[j] - m_new);   // -inf -> 0
            Ss[r][c0 + j] = p;
            psum += p;
        }
        float factor = __expf(m_old - m_new);    // first tile: exp(-inf)=0
#pragma unroll
        for (int i = 0; i < 16; i++) o_acc[i] *= factor;
        red2[r][q4] = psum;
        __syncthreads();

        if (q4 == 0) {
            l_s[r] = l_s[r] * factor + red2[r][0] + red2[r][1] + red2[r][2] + red2[r][3];
            m_s[r] = m_new;
        }

        // O += P V (row r, dims d0..d0+15)
#pragma unroll
        for (int c = 0; c < FAN; c++) {
            float p = Ss[r][c];
#pragma unroll
            for (int dd = 0; dd < 16; dd++) o_acc[dd] += p * Vs[c][d0 + dd];
        }
        __syncthreads();   // protects Ks/Vs/Ss reuse and orders m_s/l_s writes
    }

    float linv = 1.0f / l_s[r];
    float* Obase = O + ((size_t)(b * S_ + qt * FAM + r)) * HID_ + h * HD_ + d0;
#pragma unroll
    for (int dd = 0; dd < 16; dd++) Obase[dd] = o_acc[dd] * linv;
}

// ---------------------------------------------------------------------------
// Launch
// ---------------------------------------------------------------------------
extern "C" void kernel_launch(void* const* d_in, const int* in_sizes, int n_in,
                              void* d_out, int out_size)
{
    const float* hidden = (const float*)d_in[0];
    // d_in[1] = attn_mask (plain causal; implemented analytically)
    const float* wq = (const float*)d_in[2];
    const float* wk = (const float*)d_in[3];
    const float* wv = (const float*)d_in[4];
    const float* wo = (const float*)d_in[5];
    float* out = (float*)d_out;

    float *qbuf, *kbuf, *vbuf, *ctx;
    cudaGetSymbolAddress((void**)&qbuf, g_Q);
    cudaGetSymbolAddress((void**)&kbuf, g_K);
    cudaGetSymbolAddress((void**)&vbuf, g_V);
    cudaGetSymbolAddress((void**)&ctx,  g_ctx);

    const int M = B_ * S_;          // 4096
    dim3 blk(16, 16);

    // Projections
    gemm_nt_kernel<<<dim3(HID_ / GBN, M / GBM), blk>>>(hidden, wq, qbuf, M, HID_, HID_);
    gemm_nt_kernel<<<dim3((NKV_ * HD_) / GBN, M / GBM), blk>>>(hidden, wk, kbuf, M, NKV_ * HD_, HID_);
    gemm_nt_kernel<<<dim3((NKV_ * HD_) / GBN, M / GBM), blk>>>(hidden, wv, vbuf, M, NKV_ * HD_, HID_);

    // RoPE on Q and K
    rope_kernel<<<M * NH_, 32>>>(qbuf, NH_);
    rope_kernel<<<M * NKV_, 32>>>(kbuf, NKV_);

    // Attention
    flash_attn_kernel<<<dim3(S_ / FAM, NH_, B_), 256>>>(qbuf, kbuf, vbuf, ctx);

    // Output projection
    gemm_nt_kernel<<<dim3(HID_ / GBN, M / GBM), blk>>>(ctx, wo, out, M, HID_, HID_);
}

// round 3
// speedup vs baseline: 1.5570x; 1.5570x over previous
#include <cuda_runtime.h>
#include <cuda_bf16.h>
#include <cstdint>
#include <math.h>

// Problem constants
#define B_   2
#define S_   2048
#define HID_ 2048
#define NH_  32
#define NKV_ 8
#define HD_  64
#define GROUP_ 4
#define M_TOT (B_ * S_)          // 4096

// ---------------------------------------------------------------------------
// Scratch (__device__ globals; no cudaMalloc allowed)
// ---------------------------------------------------------------------------
__device__ float g_Q[(size_t)M_TOT * HID_];
__device__ float g_K[(size_t)M_TOT * NKV_ * HD_];
__device__ float g_V[(size_t)M_TOT * NKV_ * HD_];
__device__ float g_ctx[(size_t)M_TOT * HID_];

__device__ __nv_bfloat16 g_hh[(size_t)M_TOT * HID_], g_hl[(size_t)M_TOT * HID_];
__device__ __nv_bfloat16 g_wqh[(size_t)HID_ * HID_], g_wql[(size_t)HID_ * HID_];
__device__ __nv_bfloat16 g_wkh[(size_t)NKV_ * HD_ * HID_], g_wkl[(size_t)NKV_ * HD_ * HID_];
__device__ __nv_bfloat16 g_wvh[(size_t)NKV_ * HD_ * HID_], g_wvl[(size_t)NKV_ * HD_ * HID_];
__device__ __nv_bfloat16 g_woh[(size_t)HID_ * HID_], g_wol[(size_t)HID_ * HID_];
__device__ __nv_bfloat16 g_ch[(size_t)M_TOT * HID_], g_cl[(size_t)M_TOT * HID_];

__device__ float g_rsin[S_ * 32], g_rcos[S_ * 32];

// ---------------------------------------------------------------------------
// fp32 -> bf16 hi/lo split
// ---------------------------------------------------------------------------
__global__ void split_bf16(const float* __restrict__ x,
                           __nv_bfloat16* __restrict__ hi,
                           __nv_bfloat16* __restrict__ lo, int n) {
    int i = blockIdx.x * blockDim.x + threadIdx.x;
    if (i < n) {
        float v = x[i];
        __nv_bfloat16 h = __float2bfloat16(v);
        hi[i] = h;
        lo[i] = __float2bfloat16(v - __bfloat162float(h));
    }
}

// ---------------------------------------------------------------------------
// mma.sync bf16x3 GEMM: C[M,N] = A[M,K] * B[N,K]^T (both K-major / NT)
// CTA tile 128x128x32, 512 threads = 16 warps in 4x4 grid, warp tile 32x32.
// Each warp: 2 m16-tiles x 4 n8-tiles of HMMA.16816, 3 split passes.
// ---------------------------------------------------------------------------
#define BM 128
#define BN 128
#define BK 32
#define LDSS 40                      // bf16 row stride (32 + 8 pad) -> conflict-free

__device__ __forceinline__ void mma16816(float* c, const uint32_t* a, const uint32_t* b) {
    asm volatile(
        "mma.sync.aligned.m16n8k16.row.col.f32.bf16.bf16.f32 "
        "{%0,%1,%2,%3}, {%4,%5,%6,%7}, {%8,%9}, {%0,%1,%2,%3};"
        : "+f"(c[0]), "+f"(c[1]), "+f"(c[2]), "+f"(c[3])
        : "r"(a[0]), "r"(a[1]), "r"(a[2]), "r"(a[3]), "r"(b[0]), "r"(b[1]));
}

__global__ void __launch_bounds__(512, 1) gemm_mma(
    const __nv_bfloat16* __restrict__ Ah, const __nv_bfloat16* __restrict__ Al,
    const __nv_bfloat16* __restrict__ Bh, const __nv_bfloat16* __restrict__ Bl,
    float* __restrict__ C, int M, int N, int K)
{
    __shared__ __nv_bfloat16 sAh[BM * LDSS], sAl[BM * LDSS];
    __shared__ __nv_bfloat16 sBh[BN * LDSS], sBl[BN * LDSS];

    const int tid = threadIdx.x;
    const int warp = tid >> 5, lane = tid & 31;
    const int wm = (warp >> 2) * 32;       // warp m offset 0..96
    const int wn = (warp & 3) * 32;        // warp n offset 0..96
    const int g = lane >> 2, t = lane & 3;
    const int m0 = blockIdx.y * BM, n0 = blockIdx.x * BN;

    // gmem->smem mapping: 512 threads, each 1 uint4 (8 bf16) per buffer per chunk
    const int lrow = tid >> 2, lq = tid & 3;

    float acc[2][4][4];
#pragma unroll
    for (int i = 0; i < 2; i++)
#pragma unroll
        for (int j = 0; j < 4; j++)
#pragma unroll
            for (int x = 0; x < 4; x++) acc[i][j][x] = 0.f;

    for (int kc = 0; kc < K; kc += BK) {
        {
            size_t ga = (size_t)(m0 + lrow) * K + kc + lq * 8;
            size_t gb = (size_t)(n0 + lrow) * K + kc + lq * 8;
            uint32_t so = lrow * LDSS + lq * 8;
            *(uint4*)&sAh[so] = *(const uint4*)&Ah[ga];
            *(uint4*)&sAl[so] = *(const uint4*)&Al[ga];
            *(uint4*)&sBh[so] = *(const uint4*)&Bh[gb];
            *(uint4*)&sBl[so] = *(const uint4*)&Bl[gb];
        }
        __syncthreads();

#pragma unroll
        for (int ks = 0; ks < 2; ks++) {
            const int kb = ks * 16 + 2 * t;
            uint32_t afh[2][4], afl[2][4], bfh[4][2], bfl[4][2];
#pragma unroll
            for (int mi = 0; mi < 2; mi++) {
                int r = wm + mi * 16 + g;
                afh[mi][0] = *(const uint32_t*)&sAh[r * LDSS + kb];
                afh[mi][1] = *(const uint32_t*)&sAh[(r + 8) * LDSS + kb];
                afh[mi][2] = *(const uint32_t*)&sAh[r * LDSS + kb + 8];
                afh[mi][3] = *(const uint32_t*)&sAh[(r + 8) * LDSS + kb + 8];
                afl[mi][0] = *(const uint32_t*)&sAl[r * LDSS + kb];
                afl[mi][1] = *(const uint32_t*)&sAl[(r + 8) * LDSS + kb];
                afl[mi][2] = *(const uint32_t*)&sAl[r * LDSS + kb + 8];
                afl[mi][3] = *(const uint32_t*)&sAl[(r + 8) * LDSS + kb + 8];
            }
#pragma unroll
            for (int ni = 0; ni < 4; ni++) {
                int c = wn + ni * 8 + g;
                bfh[ni][0] = *(const uint32_t*)&sBh[c * LDSS + kb];
                bfh[ni][1] = *(const uint32_t*)&sBh[c * LDSS + kb + 8];
                bfl[ni][0] = *(const uint32_t*)&sBl[c * LDSS + kb];
                bfl[ni][1] = *(const uint32_t*)&sBl[c * LDSS + kb + 8];
            }
#pragma unroll
            for (int mi = 0; mi < 2; mi++)
#pragma unroll
                for (int ni = 0; ni < 4; ni++) {
                    mma16816(acc[mi][ni], afh[mi], bfh[ni]);
                    mma16816(acc[mi][ni], afh[mi], bfl[ni]);
                    mma16816(acc[mi][ni], afl[mi], bfh[ni]);
                }
        }
        __syncthreads();
    }

    // Epilogue
#pragma unroll
    for (int mi = 0; mi < 2; mi++) {
        int r = m0 + wm + mi * 16 + g;
#pragma unroll
        for (int ni = 0; ni < 4; ni++) {
            int c = n0 + wn + ni * 8 + 2 * t;
            *(float2*)&C[(size_t)r * N + c] = make_float2(acc[mi][ni][0], acc[mi][ni][1]);
            *(float2*)&C[(size_t)(r + 8) * N + c] = make_float2(acc[mi][ni][2], acc[mi][ni][3]);
        }
    }
}

// ---------------------------------------------------------------------------
// RoPE: fp64 table (tiny) + fp32 memory-bound apply
// ---------------------------------------------------------------------------
__global__ void rope_table_kernel() {
    int i = blockIdx.x * blockDim.x + threadIdx.x;   // S_*32
    int s = i >> 5, f = i & 31;
    double inv_freq = exp(-(double)f / 32.0 * log(10000.0));
    double sd, cd;
    sincos((double)s * inv_freq, &sd, &cd);
    g_rsin[i] = (float)sd;
    g_rcos[i] = (float)cd;
}
__global__ void rope_apply_kernel(float* __restrict__ X, int nheads) {
    int idx = blockIdx.x * blockDim.x + threadIdx.x;  // M_TOT*nheads*32
    int i = idx & 31;
    int bh = idx >> 5;
    int h = bh % nheads;
    int bs = bh / nheads;
    int s = bs & (S_ - 1);
    float c = g_rcos[s * 32 + i], sn = g_rsin[s * 32 + i];
    float* p = X + (size_t)bs * nheads * HD_ + (size_t)h * HD_;
    float x1 = p[i], x2 = p[i + 32];
    p[i] = x1 * c - x2 * sn;
    p[i + 32] = x2 * c + x1 * sn;
}

// ---------------------------------------------------------------------------
// Flash attention (fp32, causal) — verified correct in R1
// ---------------------------------------------------------------------------
#define FAM 64
#define FAN 32
__global__ void __launch_bounds__(256) flash_attn_kernel(
    const float* __restrict__ Q, const float* __restrict__ K,
    const float* __restrict__ V, float* __restrict__ O)
{
    __shared__ float Qs[FAM][HD_ + 1];
    __shared__ float Ks[FAN][HD_ + 1];
    __shared__ float Vs[FAN][HD_ + 1];
    __shared__ float Ss[FAM][FAN + 1];
    __shared__ float m_s[FAM], l_s[FAM];
    __shared__ float red1[FAM][4], red2[FAM][4];

    const int tid = threadIdx.x;
    const int b = blockIdx.z, h = blockIdx.y, qt = blockIdx.x;
    const int kvh = h / GROUP_;
    const int r = tid >> 2;
    const int q4 = tid & 3;
    const int c0 = q4 * 8;
    const int d0 = q4 * 16;
    const float scale = 0.125f;

    const float* Qbase = Q + ((size_t)(b * S_ + qt * FAM)) * HID_ + h * HD_;
    const float* Kbase = K + (size_t)b * S_ * (NKV_ * HD_) + kvh * HD_;
    const float* Vbase = V + (size_t)b * S_ * (NKV_ * HD_) + kvh * HD_;

#pragma unroll
    for (int i = 0; i < 16; i++) {
        int idx = tid + i * 256;
        int rr = idx >> 6, cc = idx & 63;
        Qs[rr][cc] = Qbase[(size_t)rr * HID_ + cc];
    }
    if (tid < FAM) { m_s[tid] = -INFINITY; l_s[tid] = 0.f; }

    float o_acc[16];
#pragma unroll
    for (int i = 0; i < 16; i++) o_acc[i] = 0.f;
    __syncthreads();

    const int ntiles = 2 * qt + 2;
    for (int kt = 0; kt < ntiles; kt++) {
#pragma unroll
        for (int i = 0; i < 8; i++) {
            int idx = tid + i * 256;
            int rr = idx >> 6, cc = idx & 63;
            size_t goff = ((size_t)(kt * FAN + rr)) * (NKV_ * HD_) + cc;
            Ks[rr][cc] = Kbase[goff];
            Vs[rr][cc] = Vbase[goff];
        }
        __syncthreads();

        float sacc[8];
#pragma unroll
        for (int j = 0; j < 8; j++) sacc[j] = 0.f;
#pragma unroll
        for (int k = 0; k < HD_; k++) {
            float qv = Qs[r][k];
#pragma unroll
            for (int j = 0; j < 8; j++) sacc[j] += qv * Ks[c0 + j][k];
        }
        const int grow = qt * FAM + r;
        float mx = -INFINITY;
#pragma unroll
        for (int j = 0; j < 8; j++) {
            int gcol = kt * FAN + c0 + j;
            float s = (gcol <= grow) ? sacc[j] * scale : -INFINITY;
            sacc[j] = s;
            mx = fmaxf(mx, s);
        }
        red1[r][q4] = mx;
        __syncthreads();

        float m_old = m_s[r];
        float m_new = fmaxf(m_old,
            fmaxf(fmaxf(red1[r][0], red1[r][1]), fmaxf(red1[r][2], red1[r][3])));
        float psum = 0.f;
#pragma unroll
        for (int j = 0; j < 8; j++) {
            float p = __expf(sacc[j] - m_new);
            Ss[r][c0 + j] = p;
            psum += p;
        }
        float factor = __expf(m_old - m_new);
#pragma unroll
        for (int i = 0; i < 16; i++) o_acc[i] *= factor;
        red2[r][q4] = psum;
        __syncthreads();

        if (q4 == 0) {
            l_s[r] = l_s[r] * factor + red2[r][0] + red2[r][1] + red2[r][2] + red2[r][3];
            m_s[r] = m_new;
        }

#pragma unroll
        for (int c = 0; c < FAN; c++) {
            float p = Ss[r][c];
#pragma unroll
            for (int dd = 0; dd < 16; dd++) o_acc[dd] += p * Vs[c][d0 + dd];
        }
        __syncthreads();
    }

    float linv = 1.0f / l_s[r];
    float* Obase = O + ((size_t)(b * S_ + qt * FAM + r)) * HID_ + h * HD_ + d0;
#pragma unroll
    for (int dd = 0; dd < 16; dd++) Obase[dd] = o_acc[dd] * linv;
}

// ---------------------------------------------------------------------------
// Launch
// ---------------------------------------------------------------------------
extern "C" void kernel_launch(void* const* d_in, const int* in_sizes, int n_in,
                              void* d_out, int out_size)
{
    const float* hidden = (const float*)d_in[0];
    const float* wq = (const float*)d_in[2];
    const float* wk = (const float*)d_in[3];
    const float* wv = (const float*)d_in[4];
    const float* wo = (const float*)d_in[5];
    float* out = (float*)d_out;

    float *qbuf, *kbuf, *vbuf, *ctx;
    cudaGetSymbolAddress((void**)&qbuf, g_Q);
    cudaGetSymbolAddress((void**)&kbuf, g_K);
    cudaGetSymbolAddress((void**)&vbuf, g_V);
    cudaGetSymbolAddress((void**)&ctx, g_ctx);

    __nv_bfloat16 *hh, *hl, *wqh, *wql, *wkh, *wkl, *wvh, *wvl, *woh, *wol, *ch, *cl;
    cudaGetSymbolAddress((void**)&hh, g_hh);   cudaGetSymbolAddress((void**)&hl, g_hl);
    cudaGetSymbolAddress((void**)&wqh, g_wqh); cudaGetSymbolAddress((void**)&wql, g_wql);
    cudaGetSymbolAddress((void**)&wkh, g_wkh); cudaGetSymbolAddress((void**)&wkl, g_wkl);
    cudaGetSymbolAddress((void**)&wvh, g_wvh); cudaGetSymbolAddress((void**)&wvl, g_wvl);
    cudaGetSymbolAddress((void**)&woh, g_woh); cudaGetSymbolAddress((void**)&wol, g_wol);
    cudaGetSymbolAddress((void**)&ch, g_ch);   cudaGetSymbolAddress((void**)&cl, g_cl);

    const int NKVD = NKV_ * HD_;   // 512

    // Split fp32 -> bf16 hi/lo
    {
        int n1 = M_TOT * HID_;
        split_bf16<<<(n1 + 255) / 256, 256>>>(hidden, hh, hl, n1);
        int n2 = HID_ * HID_;
        split_bf16<<<(n2 + 255) / 256, 256>>>(wq, wqh, wql, n2);
        int n3 = NKVD * HID_;
        split_bf16<<<(n3 + 255) / 256, 256>>>(wk, wkh, wkl, n3);
        split_bf16<<<(n3 + 255) / 256, 256>>>(wv, wvh, wvl, n3);
        split_bf16<<<(n2 + 255) / 256, 256>>>(wo, woh, wol, n2);
    }

    rope_table_kernel<<<(S_ * 32) / 256, 256>>>();

    // Projections (tensor cores via mma.sync)
    gemm_mma<<<dim3(HID_ / BN, M_TOT / BM), 512>>>(hh, hl, wqh, wql, qbuf, M_TOT, HID_, HID_);
    gemm_mma<<<dim3(NKVD / BN, M_TOT / BM), 512>>>(hh, hl, wkh, wkl, kbuf, M_TOT, NKVD, HID_);
    gemm_mma<<<dim3(NKVD / BN, M_TOT / BM), 512>>>(hh, hl, wvh, wvl, vbuf, M_TOT, NKVD, HID_);

    // RoPE
    rope_apply_kernel<<<(M_TOT * NH_ * 32) / 256, 256>>>(qbuf, NH_);
    rope_apply_kernel<<<(M_TOT * NKV_ * 32) / 256, 256>>>(kbuf, NKV_);

    // Attention
    flash_attn_kernel<<<dim3(S_ / FAM, NH_, B_), 256>>>(qbuf, kbuf, vbuf, ctx);

    // O projection
    {
        int n1 = M_TOT * HID_;
        split_bf16<<<(n1 + 255) / 256, 256>>>(ctx, ch, cl, n1);
    }
    gemm_mma<<<dim3(HID_ / BN, M_TOT / BM), 512>>>(ch, cl, woh, wol, out, M_TOT, HID_, HID_);
}

// round 4
// speedup vs baseline: 4.7836x; 3.0723x over previous
#include <cuda_runtime.h>
#include <cuda_bf16.h>
#include <cstdint>
#include <math.h>

// Problem constants
#define B_   2
#define S_   2048
#define HID_ 2048
#define NH_  32
#define NKV_ 8
#define HD_  64
#define GROUP_ 4
#define M_TOT (B_ * S_)          // 4096
#define NKVD (NKV_ * HD_)        // 512

// ---------------------------------------------------------------------------
// Scratch (__device__ globals; no cudaMalloc allowed)
// ---------------------------------------------------------------------------
__device__ float g_Q[(size_t)M_TOT * HID_];
__device__ float g_K[(size_t)M_TOT * NKVD];
__device__ float g_V[(size_t)M_TOT * NKVD];

__device__ __nv_bfloat16 g_hh[(size_t)M_TOT * HID_], g_hl[(size_t)M_TOT * HID_];
__device__ __nv_bfloat16 g_wqh[(size_t)HID_ * HID_], g_wql[(size_t)HID_ * HID_];
__device__ __nv_bfloat16 g_wkh[(size_t)NKVD * HID_], g_wkl[(size_t)NKVD * HID_];
__device__ __nv_bfloat16 g_wvh[(size_t)NKVD * HID_], g_wvl[(size_t)NKVD * HID_];
__device__ __nv_bfloat16 g_woh[(size_t)HID_ * HID_], g_wol[(size_t)HID_ * HID_];
__device__ __nv_bfloat16 g_qh[(size_t)M_TOT * HID_], g_ql[(size_t)M_TOT * HID_];
__device__ __nv_bfloat16 g_kh[(size_t)M_TOT * NKVD], g_kl[(size_t)M_TOT * NKVD];
__device__ __nv_bfloat16 g_vh[(size_t)M_TOT * NKVD], g_vl[(size_t)M_TOT * NKVD];
__device__ __nv_bfloat16 g_ch[(size_t)M_TOT * HID_], g_cl[(size_t)M_TOT * HID_];

__device__ float g_rsin[S_ * 32], g_rcos[S_ * 32];

// ---------------------------------------------------------------------------
// Helpers
// ---------------------------------------------------------------------------
__device__ __forceinline__ uint32_t smem_u32(const void* p) {
    uint32_t a;
    asm("{ .reg .u64 t; cvta.to.shared.u64 t, %1; cvt.u32.u64 %0, t; }" : "=r"(a) : "l"(p));
    return a;
}
__device__ __forceinline__ void cp16(uint32_t dst, const void* src) {
    asm volatile("cp.async.cg.shared.global [%0], [%1], 16;" :: "r"(dst), "l"(src));
}
__device__ __forceinline__ void mma16816(float* c, const uint32_t* a, const uint32_t* b) {
    asm volatile(
        "mma.sync.aligned.m16n8k16.row.col.f32.bf16.bf16.f32 "
        "{%0,%1,%2,%3}, {%4,%5,%6,%7}, {%8,%9}, {%0,%1,%2,%3};"
        : "+f"(c[0]), "+f"(c[1]), "+f"(c[2]), "+f"(c[3])
        : "r"(a[0]), "r"(a[1]), "r"(a[2]), "r"(a[3]), "r"(b[0]), "r"(b[1]));
}
__device__ __forceinline__ uint32_t pack_bf16(float x, float y) {
    __nv_bfloat162 h = __floats2bfloat162_rn(x, y);
    return *(uint32_t*)&h;
}

// ---------------------------------------------------------------------------
// fp32 -> bf16 hi/lo split
// ---------------------------------------------------------------------------
__global__ void split_bf16(const float* __restrict__ x,
                           __nv_bfloat16* __restrict__ hi,
                           __nv_bfloat16* __restrict__ lo, int n) {
    int i = blockIdx.x * blockDim.x + threadIdx.x;
    if (i < n) {
        float v = x[i];
        __nv_bfloat16 h = __float2bfloat16(v);
        hi[i] = h;
        lo[i] = __float2bfloat16(v - __bfloat162float(h));
    }
}

// ---------------------------------------------------------------------------
// mma.sync bf16x3 GEMM with cp.async double buffering.
// C[M,N] = A[M,K]*B[N,K]^T. CTA 128x128x32, 512 thr, warp 32x32.
// ---------------------------------------------------------------------------
#define BM 128
#define BN 128
#define BK 32
#define LDSS 40
#define TILE (BM * LDSS)          // bf16 elems per buffer (10240 B)

__global__ void __launch_bounds__(512, 1) gemm_mma(
    const __nv_bfloat16* __restrict__ Ah, const __nv_bfloat16* __restrict__ Al,
    const __nv_bfloat16* __restrict__ Bh, const __nv_bfloat16* __restrict__ Bl,
    float* __restrict__ C, int M, int N, int K)
{
    extern __shared__ __nv_bfloat16 dyn[];   // 2 stages x 4 buffers x TILE

    const int tid = threadIdx.x;
    const int warp = tid >> 5, lane = tid & 31;
    const int wm = (warp >> 2) * 32;
    const int wn = (warp & 3) * 32;
    const int g = lane >> 2, t = lane & 3;
    const int m0 = blockIdx.y * BM, n0 = blockIdx.x * BN;
    const int lrow = tid >> 2, lq = tid & 3;

    const uint32_t sb = smem_u32(dyn);
    const uint32_t my_so = (lrow * LDSS + lq * 8) * 2;

    float acc[2][4][4];
#pragma unroll
    for (int i = 0; i < 2; i++)
#pragma unroll
        for (int j = 0; j < 4; j++)
#pragma unroll
            for (int x = 0; x < 4; x++) acc[i][j][x] = 0.f;

    const int nch = K / BK;

    auto issue = [&](int kc, int s) {
        uint32_t so = sb + (uint32_t)s * 4 * TILE * 2 + my_so;
        size_t ga = (size_t)(m0 + lrow) * K + kc * BK + lq * 8;
        size_t gb = (size_t)(n0 + lrow) * K + kc * BK + lq * 8;
        cp16(so,                Ah + ga);
        cp16(so + TILE * 2,     Al + ga);
        cp16(so + 2 * TILE * 2, Bh + gb);
        cp16(so + 3 * TILE * 2, Bl + gb);
        asm volatile("cp.async.commit_group;");
    };

    issue(0, 0);
    for (int kc = 0; kc < nch; kc++) {
        if (kc + 1 < nch) {
            issue(kc + 1, (kc + 1) & 1);
            asm volatile("cp.async.wait_group 1;");
        } else {
            asm volatile("cp.async.wait_group 0;");
        }
        __syncthreads();

        const __nv_bfloat16* sAh = dyn + (size_t)(kc & 1) * 4 * TILE;
        const __nv_bfloat16* sAl = sAh + TILE;
        const __nv_bfloat16* sBh = sAh + 2 * TILE;
        const __nv_bfloat16* sBl = sAh + 3 * TILE;

#pragma unroll
        for (int ks = 0; ks < 2; ks++) {
            const int kb = ks * 16 + 2 * t;
            uint32_t afh[2][4], afl[2][4], bfh[4][2], bfl[4][2];
#pragma unroll
            for (int mi = 0; mi < 2; mi++) {
                int r = wm + mi * 16 + g;
                afh[mi][0] = *(const uint32_t*)&sAh[r * LDSS + kb];
                afh[mi][1] = *(const uint32_t*)&sAh[(r + 8) * LDSS + kb];
                afh[mi][2] = *(const uint32_t*)&sAh[r * LDSS + kb + 8];
                afh[mi][3] = *(const uint32_t*)&sAh[(r + 8) * LDSS + kb + 8];
                afl[mi][0] = *(const uint32_t*)&sAl[r * LDSS + kb];
                afl[mi][1] = *(const uint32_t*)&sAl[(r + 8) * LDSS + kb];
                afl[mi][2] = *(const uint32_t*)&sAl[r * LDSS + kb + 8];
                afl[mi][3] = *(const uint32_t*)&sAl[(r + 8) * LDSS + kb + 8];
            }
#pragma unroll
            for (int ni = 0; ni < 4; ni++) {
                int c = wn + ni * 8 + g;
                bfh[ni][0] = *(const uint32_t*)&sBh[c * LDSS + kb];
                bfh[ni][1] = *(const uint32_t*)&sBh[c * LDSS + kb + 8];
                bfl[ni][0] = *(const uint32_t*)&sBl[c * LDSS + kb];
                bfl[ni][1] = *(const uint32_t*)&sBl[c * LDSS + kb + 8];
            }
#pragma unroll
            for (int mi = 0; mi < 2; mi++)
#pragma unroll
                for (int ni = 0; ni < 4; ni++) {
                    mma16816(acc[mi][ni], afh[mi], bfh[ni]);
                    mma16816(acc[mi][ni], afh[mi], bfl[ni]);
                    mma16816(acc[mi][ni], afl[mi], bfh[ni]);
                }
        }
        __syncthreads();
    }

#pragma unroll
    for (int mi = 0; mi < 2; mi++) {
        int r = m0 + wm + mi * 16 + g;
#pragma unroll
        for (int ni = 0; ni < 4; ni++) {
            int c = n0 + wn + ni * 8 + 2 * t;
            *(float2*)&C[(size_t)r * N + c] = make_float2(acc[mi][ni][0], acc[mi][ni][1]);
            *(float2*)&C[(size_t)(r + 8) * N + c] = make_float2(acc[mi][ni][2], acc[mi][ni][3]);
        }
    }
}

// ---------------------------------------------------------------------------
// RoPE: table + apply-and-split (fp32 in, bf16 hi/lo out)
// ---------------------------------------------------------------------------
__global__ void rope_table_kernel() {
    int i = blockIdx.x * blockDim.x + threadIdx.x;
    int s = i >> 5, f = i & 31;
    double inv_freq = exp(-(double)f / 32.0 * log(10000.0));
    double sd, cd;
    sincos((double)s * inv_freq, &sd, &cd);
    g_rsin[i] = (float)sd;
    g_rcos[i] = (float)cd;
}
__global__ void rope_split_kernel(const float* __restrict__ X,
                                  __nv_bfloat16* __restrict__ Xh,
                                  __nv_bfloat16* __restrict__ Xl, int nheads) {
    int idx = blockIdx.x * blockDim.x + threadIdx.x;
    int i = idx & 31;
    int bh = idx >> 5;
    int h = bh % nheads;
    int bs = bh / nheads;
    int s = bs & (S_ - 1);
    float c = g_rcos[s * 32 + i], sn = g_rsin[s * 32 + i];
    size_t base = (size_t)bs * nheads * HD_ + (size_t)h * HD_;
    float x1 = X[base + i], x2 = X[base + i + 32];
    float y1 = x1 * c - x2 * sn;
    float y2 = x2 * c + x1 * sn;
    __nv_bfloat16 h1 = __float2bfloat16(y1);
    __nv_bfloat16 h2 = __float2bfloat16(y2);
    Xh[base + i] = h1;
    Xh[base + i + 32] = h2;
    Xl[base + i] = __float2bfloat16(y1 - __bfloat162float(h1));
    Xl[base + i + 32] = __float2bfloat16(y2 - __bfloat162float(h2));
}

// ---------------------------------------------------------------------------
// Tensor-core flash attention (bf16x3, causal).
// grid=(S/128, NH, B), block=256 (8 warps). Warp w: q rows w*16..w*16+15.
// K-tiles of 64 keys. Scores+softmax+P in registers, V^T in smem.
// Writes context split into bf16 hi/lo for O-projection.
// ---------------------------------------------------------------------------
#define LDK 72
__global__ void __launch_bounds__(256, 1) flash_mma(
    const __nv_bfloat16* __restrict__ qh, const __nv_bfloat16* __restrict__ ql,
    const __nv_bfloat16* __restrict__ kh, const __nv_bfloat16* __restrict__ kl,
    const __nv_bfloat16* __restrict__ vh, const __nv_bfloat16* __restrict__ vl,
    __nv_bfloat16* __restrict__ ch, __nv_bfloat16* __restrict__ cl)
{
    __shared__ __nv_bfloat16 sKh[64 * LDK], sKl[64 * LDK];
    __shared__ __nv_bfloat16 sVh[64 * LDK], sVl[64 * LDK];   // transposed: [dim][key]

    const int tid = threadIdx.x;
    const int w = tid >> 5, lane = tid & 31;
    const int g = lane >> 2, t = lane & 3;
    const int qt = blockIdx.x, h = blockIdx.y, b = blockIdx.z;
    const int kvh = h / GROUP_;
    const int row_base = qt * 128 + w * 16;         // warp's first q row (in-seq)
    const float SCALE = 0.125f;

    // Q fragments (held in registers for the whole block)
    uint32_t aqh[4][4], aql[4][4];
    {
        const __nv_bfloat16* qb = qh + ((size_t)(b * S_ + row_base)) * HID_ + h * HD_;
        const __nv_bfloat16* qb2 = ql + ((size_t)(b * S_ + row_base)) * HID_ + h * HD_;
#pragma unroll
        for (int j = 0; j < 4; j++) {
            int k0 = j * 16 + 2 * t;
            aqh[j][0] = *(const uint32_t*)&qb[(size_t)g * HID_ + k0];
            aqh[j][1] = *(const uint32_t*)&qb[(size_t)(g + 8) * HID_ + k0];
            aqh[j][2] = *(const uint32_t*)&qb[(size_t)g * HID_ + k0 + 8];
            aqh[j][3] = *(const uint32_t*)&qb[(size_t)(g + 8) * HID_ + k0 + 8];
            aql[j][0] = *(const uint32_t*)&qb2[(size_t)g * HID_ + k0];
            aql[j][1] = *(const uint32_t*)&qb2[(size_t)(g + 8) * HID_ + k0];
            aql[j][2] = *(const uint32_t*)&qb2[(size_t)g * HID_ + k0 + 8];
            aql[j][3] = *(const uint32_t*)&qb2[(size_t)(g + 8) * HID_ + k0 + 8];
        }
    }

    float o[8][4];
#pragma unroll
    for (int i = 0; i < 8; i++)
#pragma unroll
        for (int j = 0; j < 4; j++) o[i][j] = 0.f;
    float m0 = -INFINITY, m1 = -INFINITY, l0 = 0.f, l1 = 0.f;

    const int ntiles = 2 * qt + 2;
    for (int kt = 0; kt < ntiles; kt++) {
        // --- cooperative load of K tile and transposed V tile ---
        {
            const size_t grow0 = (size_t)(b * S_ + kt * 64);
#pragma unroll
            for (int i = 0; i < 2; i++) {
                int idx = tid + i * 256;          // 0..511
                int r = idx >> 3, q = idx & 7;    // key row, 8-elem chunk
                size_t go = (grow0 + r) * NKVD + kvh * HD_ + q * 8;
                *(uint4*)&sKh[r * LDK + q * 8] = *(const uint4*)&kh[go];
                *(uint4*)&sKl[r * LDK + q * 8] = *(const uint4*)&kl[go];
                // V transpose: element [key r][dim q*8+e] -> sV[dim][key]
                uint4 vh8 = *(const uint4*)&vh[go];
                uint4 vl8 = *(const uint4*)&vl[go];
                const __nv_bfloat16* ph = (const __nv_bfloat16*)&vh8;
                const __nv_bfloat16* pl = (const __nv_bfloat16*)&vl8;
#pragma unroll
                for (int e = 0; e < 8; e++) {
                    sVh[(q * 8 + e) * LDK + r] = ph[e];
                    sVl[(q * 8 + e) * LDK + r] = pl[e];
                }
            }
        }
        __syncthreads();

        const bool skip = (kt * 64) > (row_base + 15);
        if (!skip) {
            // --- S = scale * Q K^T ---
            float s[8][4];
#pragma unroll
            for (int i = 0; i < 8; i++)
#pragma unroll
                for (int j = 0; j < 4; j++) s[i][j] = 0.f;
#pragma unroll
            for (int ni = 0; ni < 8; ni++) {
                int key = ni * 8 + g;
#pragma unroll
                for (int j = 0; j < 4; j++) {
                    int kb = j * 16 + 2 * t;
                    uint32_t bh2[2], bl2[2];
                    bh2[0] = *(const uint32_t*)&sKh[key * LDK + kb];
                    bh2[1] = *(const uint32_t*)&sKh[key * LDK + kb + 8];
                    bl2[0] = *(const uint32_t*)&sKl[key * LDK + kb];
                    bl2[1] = *(const uint32_t*)&sKl[key * LDK + kb + 8];
                    mma16816(s[ni], aqh[j], bh2);
                    mma16816(s[ni], aqh[j], bl2);
                    mma16816(s[ni], aql[j], bh2);
                }
            }
            const int r0 = row_base + g, r1 = row_base + g + 8;
            const bool need_mask = (kt * 64 + 63) > r0;   // conservative per-thread
#pragma unroll
            for (int ni = 0; ni < 8; ni++) {
                int c0 = kt * 64 + ni * 8 + 2 * t;
                s[ni][0] *= SCALE; s[ni][1] *= SCALE; s[ni][2] *= SCALE; s[ni][3] *= SCALE;
                if (need_mask || (kt * 64 + 63) > r1) {
                    if (c0 > r0)     s[ni][0] = -INFINITY;
                    if (c0 + 1 > r0) s[ni][1] = -INFINITY;
                    if (c0 > r1)     s[ni][2] = -INFINITY;
                    if (c0 + 1 > r1) s[ni][3] = -INFINITY;
                }
            }
            // --- row max (over 16 cols held, then quad shfl) ---
            float mx0 = -INFINITY, mx1 = -INFINITY;
#pragma unroll
            for (int ni = 0; ni < 8; ni++) {
                mx0 = fmaxf(mx0, fmaxf(s[ni][0], s[ni][1]));
                mx1 = fmaxf(mx1, fmaxf(s[ni][2], s[ni][3]));
            }
            mx0 = fmaxf(mx0, __shfl_xor_sync(0xffffffff, mx0, 1));
            mx0 = fmaxf(mx0, __shfl_xor_sync(0xffffffff, mx0, 2));
            mx1 = fmaxf(mx1, __shfl_xor_sync(0xffffffff, mx1, 1));
            mx1 = fmaxf(mx1, __shfl_xor_sync(0xffffffff, mx1, 2));

            float mn0 = fmaxf(m0, mx0), mn1 = fmaxf(m1, mx1);
            float f0 = __expf(m0 - mn0), f1 = __expf(m1 - mn1);
            m0 = mn0; m1 = mn1;

            // --- P = exp(S - m), rowsum ---
            float sum0 = 0.f, sum1 = 0.f;
#pragma unroll
            for (int ni = 0; ni < 8; ni++) {
                s[ni][0] = __expf(s[ni][0] - mn0);
                s[ni][1] = __expf(s[ni][1] - mn0);
                s[ni][2] = __expf(s[ni][2] - mn1);
                s[ni][3] = __expf(s[ni][3] - mn1);
                sum0 += s[ni][0] + s[ni][1];
                sum1 += s[ni][2] + s[ni][3];
            }
            sum0 += __shfl_xor_sync(0xffffffff, sum0, 1);
            sum0 += __shfl_xor_sync(0xffffffff, sum0, 2);
            sum1 += __shfl_xor_sync(0xffffffff, sum1, 1);
            sum1 += __shfl_xor_sync(0xffffffff, sum1, 2);
            l0 = l0 * f0 + sum0;
            l1 = l1 * f1 + sum1;

            // --- rescale o ---
#pragma unroll
            for (int nd = 0; nd < 8; nd++) {
                o[nd][0] *= f0; o[nd][1] *= f0;
                o[nd][2] *= f1; o[nd][3] *= f1;
            }

            // --- repack P into A fragments (hi/lo) ---
            uint32_t pfh[4][4], pfl[4][4];
#pragma unroll
            for (int j = 0; j < 4; j++) {
                float p00 = s[2 * j][0],     p01 = s[2 * j][1];
                float p10 = s[2 * j][2],     p11 = s[2 * j][3];
                float p20 = s[2 * j + 1][0], p21 = s[2 * j + 1][1];
                float p30 = s[2 * j + 1][2], p31 = s[2 * j + 1][3];
                pfh[j][0] = pack_bf16(p00, p01);
                pfh[j][1] = pack_bf16(p10, p11);
                pfh[j][2] = pack_bf16(p20, p21);
                pfh[j][3] = pack_bf16(p30, p31);
                __nv_bfloat162* hp;
                hp = (__nv_bfloat162*)&pfh[j][0];
                pfl[j][0] = pack_bf16(p00 - __bfloat162float(hp->x), p01 - __bfloat162float(hp->y));
                hp = (__nv_bfloat162*)&pfh[j][1];
                pfl[j][1] = pack_bf16(p10 - __bfloat162float(hp->x), p11 - __bfloat162float(hp->y));
                hp = (__nv_bfloat162*)&pfh[j][2];
                pfl[j][2] = pack_bf16(p20 - __bfloat162float(hp->x), p21 - __bfloat162float(hp->y));
                hp = (__nv_bfloat162*)&pfh[j][3];
                pfl[j][3] = pack_bf16(p30 - __bfloat162float(hp->x), p31 - __bfloat162float(hp->y));
            }

            // --- O += P V ---
#pragma unroll
            for (int nd = 0; nd < 8; nd++) {
                int d = nd * 8 + g;
#pragma unroll
                for (int j = 0; j < 4; j++) {
                    int kb = j * 16 + 2 * t;
                    uint32_t bh2[2], bl2[2];
                    bh2[0] = *(const uint32_t*)&sVh[d * LDK + kb];
                    bh2[1] = *(const uint32_t*)&sVh[d * LDK + kb + 8];
                    bl2[0] = *(const uint32_t*)&sVl[d * LDK + kb];
                    bl2[1] = *(const uint32_t*)&sVl[d * LDK + kb + 8];
                    mma16816(o[nd], pfh[j], bh2);
                    mma16816(o[nd], pfh[j], bl2);
                    mma16816(o[nd], pfl[j], bh2);
                }
            }
        }
        __syncthreads();
    }

    // --- normalize and write bf16 hi/lo context ---
    float li0 = 1.0f / l0, li1 = 1.0f / l1;
    const size_t r0 = (size_t)(b * S_ + row_base + g) * HID_ + h * HD_;
    const size_t r1 = (size_t)(b * S_ + row_base + g + 8) * HID_ + h * HD_;
#pragma unroll
    for (int nd = 0; nd < 8; nd++) {
        int c = nd * 8 + 2 * t;
        float v0 = o[nd][0] * li0, v1 = o[nd][1] * li0;
        float v2 = o[nd][2] * li1, v3 = o[nd][3] * li1;
        uint32_t h01 = pack_bf16(v0, v1), h23 = pack_bf16(v2, v3);
        __nv_bfloat162* hp;
        hp = (__nv_bfloat162*)&h01;
        uint32_t l01 = pack_bf16(v0 - __bfloat162float(hp->x), v1 - __bfloat162float(hp->y));
        hp = (__nv_bfloat162*)&h23;
        uint32_t l23 = pack_bf16(v2 - __bfloat162float(hp->x), v3 - __bfloat162float(hp->y));
        *(uint32_t*)&ch[r0 + c] = h01;
        *(uint32_t*)&cl[r0 + c] = l01;
        *(uint32_t*)&ch[r1 + c] = h23;
        *(uint32_t*)&cl[r1 + c] = l23;
    }
}

// ---------------------------------------------------------------------------
// Launch
// ---------------------------------------------------------------------------
extern "C" void kernel_launch(void* const* d_in, const int* in_sizes, int n_in,
                              void* d_out, int out_size)
{
    const float* hidden = (const float*)d_in[0];
    const float* wq = (const float*)d_in[2];
    const float* wk = (const float*)d_in[3];
    const float* wv = (const float*)d_in[4];
    const float* wo = (const float*)d_in[5];
    float* out = (float*)d_out;

    float *qbuf, *kbuf, *vbuf;
    cudaGetSymbolAddress((void**)&qbuf, g_Q);
    cudaGetSymbolAddress((void**)&kbuf, g_K);
    cudaGetSymbolAddress((void**)&vbuf, g_V);

    __nv_bfloat16 *hh, *hl, *wqh, *wql, *wkh, *wkl, *wvh, *wvl, *woh, *wol;
    __nv_bfloat16 *qh, *ql, *kh, *kl, *vh, *vl, *ch, *cl;
    cudaGetSymbolAddress((void**)&hh, g_hh);   cudaGetSymbolAddress((void**)&hl, g_hl);
    cudaGetSymbolAddress((void**)&wqh, g_wqh); cudaGetSymbolAddress((void**)&wql, g_wql);
    cudaGetSymbolAddress((void**)&wkh, g_wkh); cudaGetSymbolAddress((void**)&wkl, g_wkl);
    cudaGetSymbolAddress((void**)&wvh, g_wvh); cudaGetSymbolAddress((void**)&wvl, g_wvl);
    cudaGetSymbolAddress((void**)&woh, g_woh); cudaGetSymbolAddress((void**)&wol, g_wol);
    cudaGetSymbolAddress((void**)&qh, g_qh);   cudaGetSymbolAddress((void**)&ql, g_ql);
    cudaGetSymbolAddress((void**)&kh, g_kh);   cudaGetSymbolAddress((void**)&kl, g_kl);
    cudaGetSymbolAddress((void**)&vh, g_vh);   cudaGetSymbolAddress((void**)&vl, g_vl);
    cudaGetSymbolAddress((void**)&ch, g_ch);   cudaGetSymbolAddress((void**)&cl, g_cl);

    const int GEMM_DYN = 2 * 4 * TILE * 2;   // 81920 B
    cudaFuncSetAttribute(gemm_mma, cudaFuncAttributeMaxDynamicSharedMemorySize, GEMM_DYN);

    // Split inputs to bf16 hi/lo
    {
        int n1 = M_TOT * HID_;
        split_bf16<<<(n1 + 255) / 256, 256>>>(hidden, hh, hl, n1);
        int n2 = HID_ * HID_;
        split_bf16<<<(n2 + 255) / 256, 256>>>(wq, wqh, wql, n2);
        int n3 = NKVD * HID_;
        split_bf16<<<(n3 + 255) / 256, 256>>>(wk, wkh, wkl, n3);
        split_bf16<<<(n3 + 255) / 256, 256>>>(wv, wvh, wvl, n3);
        split_bf16<<<(n2 + 255) / 256, 256>>>(wo, woh, wol, n2);
    }

    rope_table_kernel<<<(S_ * 32) / 256, 256>>>();

    // Projections
    gemm_mma<<<dim3(HID_ / BN, M_TOT / BM), 512, GEMM_DYN>>>(hh, hl, wqh, wql, qbuf, M_TOT, HID_, HID_);
    gemm_mma<<<dim3(NKVD / BN, M_TOT / BM), 512, GEMM_DYN>>>(hh, hl, wkh, wkl, kbuf, M_TOT, NKVD, HID_);
    gemm_mma<<<dim3(NKVD / BN, M_TOT / BM), 512, GEMM_DYN>>>(hh, hl, wvh, wvl, vbuf, M_TOT, NKVD, HID_);

    // RoPE + split to bf16
    rope_split_kernel<<<(M_TOT * NH_ * 32) / 256, 256>>>(qbuf, qh, ql, NH_);
    rope_split_kernel<<<(M_TOT * NKV_ * 32) / 256, 256>>>(kbuf, kh, kl, NKV_);
    {
        int n3 = M_TOT * NKVD;
        split_bf16<<<(n3 + 255) / 256, 256>>>(vbuf, vh, vl, n3);
    }

    // Tensor-core flash attention (writes split context)
    flash_mma<<<dim3(S_ / 128, NH_, B_), 256>>>(qh, ql, kh, kl, vh, vl, ch, cl);

    // O projection
    gemm_mma<<<dim3(HID_ / BN, M_TOT / BM), 512, GEMM_DYN>>>(ch, cl, woh, wol, out, M_TOT, HID_, HID_);
}

// round 6
// speedup vs baseline: 5.1902x; 1.0850x over previous
#include <cuda_runtime.h>
#include <cuda_bf16.h>
#include <cstdint>
#include <math.h>

// Problem constants
#define B_   2
#define S_   2048
#define HID_ 2048
#define NH_  32
#define NKV_ 8
#define HD_  64
#define GROUP_ 4
#define M_TOT (B_ * S_)          // 4096
#define NKVD (NKV_ * HD_)        // 512

// ---------------------------------------------------------------------------
// Scratch (__device__ globals; no cudaMalloc allowed)
// ---------------------------------------------------------------------------
__device__ float g_Q[(size_t)M_TOT * HID_];
__device__ float g_K[(size_t)M_TOT * NKVD];
__device__ float g_V[(size_t)M_TOT * NKVD];

__device__ __nv_bfloat16 g_hh[(size_t)M_TOT * HID_], g_hl[(size_t)M_TOT * HID_];
__device__ __nv_bfloat16 g_wqh[(size_t)HID_ * HID_], g_wql[(size_t)HID_ * HID_];
__device__ __nv_bfloat16 g_wkh[(size_t)NKVD * HID_], g_wkl[(size_t)NKVD * HID_];
__device__ __nv_bfloat16 g_wvh[(size_t)NKVD * HID_], g_wvl[(size_t)NKVD * HID_];
__device__ __nv_bfloat16 g_woh[(size_t)HID_ * HID_], g_wol[(size_t)HID_ * HID_];
__device__ __nv_bfloat16 g_qh[(size_t)M_TOT * HID_], g_ql[(size_t)M_TOT * HID_];
__device__ __nv_bfloat16 g_kh[(size_t)M_TOT * NKVD], g_kl[(size_t)M_TOT * NKVD];
__device__ __nv_bfloat16 g_vh[(size_t)M_TOT * NKVD], g_vl[(size_t)M_TOT * NKVD];
__device__ __nv_bfloat16 g_ch[(size_t)M_TOT * HID_], g_cl[(size_t)M_TOT * HID_];

__device__ float g_rsin[S_ * 32], g_rcos[S_ * 32];

// ---------------------------------------------------------------------------
// Helpers
// ---------------------------------------------------------------------------
__device__ __forceinline__ uint32_t smem_u32(const void* p) {
    uint32_t a;
    asm("{ .reg .u64 t; cvta.to.shared.u64 t, %1; cvt.u32.u64 %0, t; }" : "=r"(a) : "l"(p));
    return a;
}
__device__ __forceinline__ void cp16(uint32_t dst, const void* src) {
    asm volatile("cp.async.cg.shared.global [%0], [%1], 16;" :: "r"(dst), "l"(src));
}
__device__ __forceinline__ void cp_commit() {
    asm volatile("cp.async.commit_group;");
}
__device__ __forceinline__ void cp_wait1() {
    asm volatile("cp.async.wait_group 1;");
}
__device__ __forceinline__ void cp_wait0() {
    asm volatile("cp.async.wait_group 0;");
}
__device__ __forceinline__ void ldsm4(uint32_t* r, uint32_t addr) {
    asm volatile("ldmatrix.sync.aligned.m8n8.x4.shared.b16 {%0,%1,%2,%3}, [%4];"
        : "=r"(r[0]), "=r"(r[1]), "=r"(r[2]), "=r"(r[3]) : "r"(addr));
}
__device__ __forceinline__ void ldsm4t(uint32_t* r, uint32_t addr) {
    asm volatile("ldmatrix.sync.aligned.m8n8.x4.trans.shared.b16 {%0,%1,%2,%3}, [%4];"
        : "=r"(r[0]), "=r"(r[1]), "=r"(r[2]), "=r"(r[3]) : "r"(addr));
}
__device__ __forceinline__ void mma16816(float* c, const uint32_t* a, const uint32_t* b) {
    asm volatile(
        "mma.sync.aligned.m16n8k16.row.col.f32.bf16.bf16.f32 "
        "{%0,%1,%2,%3}, {%4,%5,%6,%7}, {%8,%9}, {%0,%1,%2,%3};"
        : "+f"(c[0]), "+f"(c[1]), "+f"(c[2]), "+f"(c[3])
        : "r"(a[0]), "r"(a[1]), "r"(a[2]), "r"(a[3]), "r"(b[0]), "r"(b[1]));
}
__device__ __forceinline__ uint32_t pack_bf16(float x, float y) {
    __nv_bfloat162 h = __floats2bfloat162_rn(x, y);
    return *(uint32_t*)&h;
}

// ---------------------------------------------------------------------------
// fp32 -> bf16 hi/lo split
// ---------------------------------------------------------------------------
__global__ void split_bf16(const float* __restrict__ x,
                           __nv_bfloat16* __restrict__ hi,
                           __nv_bfloat16* __restrict__ lo, int n) {
    int i = blockIdx.x * blockDim.x + threadIdx.x;
    if (i < n) {
        float v = x[i];
        __nv_bfloat16 h = __float2bfloat16(v);
        hi[i] = h;
        lo[i] = __float2bfloat16(v - __bfloat162float(h));
    }
}

// ---------------------------------------------------------------------------
// mma.sync bf16x3 GEMM, 3-stage cp.async pipeline, ldmatrix fragments.
// C[M,N] = A[M,K]*B[N,K]^T. CTA 128x128x32, 512 thr, warp 32x32.
// ---------------------------------------------------------------------------
#define BM 128
#define BN 128
#define BK 32
#define LDSS 40
#define TILE (BM * LDSS)           // bf16 elems per buffer
#define GSTG 3

__global__ void __launch_bounds__(512, 1) gemm_mma(
    const __nv_bfloat16* __restrict__ Ah, const __nv_bfloat16* __restrict__ Al,
    const __nv_bfloat16* __restrict__ Bh, const __nv_bfloat16* __restrict__ Bl,
    float* __restrict__ C, int M, int N, int K)
{
    extern __shared__ __nv_bfloat16 dyn[];   // GSTG stages x 4 buffers x TILE

    const int tid = threadIdx.x;
    const int warp = tid >> 5, lane = tid & 31;
    const int wm = (warp >> 2) * 32;
    const int wn = (warp & 3) * 32;
    const int g = lane >> 2, t = lane & 3;
    const int m0 = blockIdx.y * BM, n0 = blockIdx.x * BN;
    const int lrow = tid >> 2, lq = tid & 3;
    const int l8 = lane & 7, half = (lane >> 3) & 1, kq = lane >> 4;

    const uint32_t sb = smem_u32(dyn);
    const uint32_t my_so = (lrow * LDSS + lq * 8) * 2;

    float acc[2][4][4];
#pragma unroll
    for (int i = 0; i < 2; i++)
#pragma unroll
        for (int j = 0; j < 4; j++)
#pragma unroll
            for (int x = 0; x < 4; x++) acc[i][j][x] = 0.f;

    const int nch = K / BK;

    auto issue = [&](int kc, int st) {
        uint32_t so = sb + (uint32_t)st * 4 * TILE * 2 + my_so;
        size_t ga = (size_t)(m0 + lrow) * K + kc * BK + lq * 8;
        size_t gb = (size_t)(n0 + lrow) * K + kc * BK + lq * 8;
        cp16(so,                Ah + ga);
        cp16(so + TILE * 2,     Al + ga);
        cp16(so + 2 * TILE * 2, Bh + gb);
        cp16(so + 3 * TILE * 2, Bl + gb);
        cp_commit();
    };

    issue(0, 0);
    if (nch > 1) issue(1, 1);

    for (int kc = 0; kc < nch; kc++) {
        if (kc + 1 < nch) cp_wait1(); else cp_wait0();
        __syncthreads();
        if (kc + 2 < nch) issue(kc + 2, (kc + 2) % GSTG);

        const uint32_t sa = sb + (uint32_t)(kc % GSTG) * 4 * TILE * 2;
        const uint32_t sAh_ = sa, sAl_ = sa + TILE * 2;
        const uint32_t sBh_ = sa + 2 * TILE * 2, sBl_ = sa + 3 * TILE * 2;

#pragma unroll
        for (int ks = 0; ks < 2; ks++) {
            const int kb = ks * 16 + kq * 8;
            uint32_t afh[2][4], afl[2][4], bfh[4][2], bfl[4][2];
#pragma unroll
            for (int mi = 0; mi < 2; mi++) {
                uint32_t ad = ((wm + mi * 16 + l8 + half * 8) * LDSS + kb) * 2;
                ldsm4(afh[mi], sAh_ + ad);
                ldsm4(afl[mi], sAl_ + ad);
            }
#pragma unroll
            for (int p = 0; p < 2; p++) {
                uint32_t bd = ((wn + p * 16 + l8 + half * 8) * LDSS + kb) * 2;
                uint32_t th[4], tl[4];
                ldsm4(th, sBh_ + bd);
                ldsm4(tl, sBl_ + bd);
                bfh[2 * p][0] = th[0]; bfh[2 * p][1] = th[2];
                bfh[2 * p + 1][0] = th[1]; bfh[2 * p + 1][1] = th[3];
                bfl[2 * p][0] = tl[0]; bfl[2 * p][1] = tl[2];
                bfl[2 * p + 1][0] = tl[1]; bfl[2 * p + 1][1] = tl[3];
            }
#pragma unroll
            for (int mi = 0; mi < 2; mi++)
#pragma unroll
                for (int ni = 0; ni < 4; ni++) {
                    mma16816(acc[mi][ni], afh[mi], bfh[ni]);
                    mma16816(acc[mi][ni], afh[mi], bfl[ni]);
                    mma16816(acc[mi][ni], afl[mi], bfh[ni]);
                }
        }
    }

#pragma unroll
    for (int mi = 0; mi < 2; mi++) {
        int r = m0 + wm + mi * 16 + g;
#pragma unroll
        for (int ni = 0; ni < 4; ni++) {
            int c = n0 + wn + ni * 8 + 2 * t;
            *(float2*)&C[(size_t)r * N + c] = make_float2(acc[mi][ni][0], acc[mi][ni][1]);
            *(float2*)&C[(size_t)(r + 8) * N + c] = make_float2(acc[mi][ni][2], acc[mi][ni][3]);
        }
    }
}

// ---------------------------------------------------------------------------
// RoPE: table + apply-and-split (fp32 in, bf16 hi/lo out)
// ---------------------------------------------------------------------------
__global__ void rope_table_kernel() {
    int i = blockIdx.x * blockDim.x + threadIdx.x;
    int s = i >> 5, f = i & 31;
    double inv_freq = exp(-(double)f / 32.0 * log(10000.0));
    double sd, cd;
    sincos((double)s * inv_freq, &sd, &cd);
    g_rsin[i] = (float)sd;
    g_rcos[i] = (float)cd;
}
__global__ void rope_split_kernel(const float* __restrict__ X,
                                  __nv_bfloat16* __restrict__ Xh,
                                  __nv_bfloat16* __restrict__ Xl, int nheads) {
    int idx = blockIdx.x * blockDim.x + threadIdx.x;
    int i = idx & 31;
    int bh = idx >> 5;
    int h = bh % nheads;
    int bs = bh / nheads;
    int s = bs & (S_ - 1);
    float c = g_rcos[s * 32 + i], sn = g_rsin[s * 32 + i];
    size_t base = (size_t)bs * nheads * HD_ + (size_t)h * HD_;
    float x1 = X[base + i], x2 = X[base + i + 32];
    float y1 = x1 * c - x2 * sn;
    float y2 = x2 * c + x1 * sn;
    __nv_bfloat16 h1 = __float2bfloat16(y1);
    __nv_bfloat16 h2 = __float2bfloat16(y2);
    Xh[base + i] = h1;
    Xh[base + i + 32] = h2;
    Xl[base + i] = __float2bfloat16(y1 - __bfloat162float(h1));
    Xl[base + i + 32] = __float2bfloat16(y2 - __bfloat162float(h2));
}

// ---------------------------------------------------------------------------
// Tensor-core flash attention (bf16x3, causal), 3-stage cp.async K/V pipeline,
// ldmatrix K-frags + ldmatrix.trans V-frags (no smem transpose).
// grid=(S/128, NH, B), block=256 (8 warps). Warp w: q rows w*16..w*16+15.
// ---------------------------------------------------------------------------
#define LDK 72
#define KVT (64 * LDK)            // bf16 elems per K/V buffer
#define FSTG 3

__global__ void __launch_bounds__(256, 1) flash_mma(
    const __nv_bfloat16* __restrict__ qh, const __nv_bfloat16* __restrict__ ql,
    const __nv_bfloat16* __restrict__ kh, const __nv_bfloat16* __restrict__ kl,
    const __nv_bfloat16* __restrict__ vh, const __nv_bfloat16* __restrict__ vl,
    __nv_bfloat16* __restrict__ ch, __nv_bfloat16* __restrict__ cl)
{
    extern __shared__ __nv_bfloat16 fdyn[];   // FSTG x 4 x KVT

    const int tid = threadIdx.x;
    const int w = tid >> 5, lane = tid & 31;
    const int g = lane >> 2, t = lane & 3;
    const int l8 = lane & 7, half = (lane >> 3) & 1, kq = lane >> 4;
    const int qt = blockIdx.x, h = blockIdx.y, b = blockIdx.z;
    const int kvh = h / GROUP_;
    const int row_base = qt * 128 + w * 16;
    const float SCALE = 0.125f;
    const uint32_t sb = smem_u32(fdyn);

    // Q fragments (registers for the whole block)
    uint32_t aqh[4][4], aql[4][4];
    {
        const __nv_bfloat16* qb = qh + ((size_t)(b * S_ + row_base)) * HID_ + h * HD_;
        const __nv_bfloat16* qb2 = ql + ((size_t)(b * S_ + row_base)) * HID_ + h * HD_;
#pragma unroll
        for (int j = 0; j < 4; j++) {
            int k0 = j * 16 + 2 * t;
            aqh[j][0] = *(const uint32_t*)&qb[(size_t)g * HID_ + k0];
            aqh[j][1] = *(const uint32_t*)&qb[(size_t)(g + 8) * HID_ + k0];
            aqh[j][2] = *(const uint32_t*)&qb[(size_t)g * HID_ + k0 + 8];
            aqh[j][3] = *(const uint32_t*)&qb[(size_t)(g + 8) * HID_ + k0 + 8];
            aql[j][0] = *(const uint32_t*)&qb2[(size_t)g * HID_ + k0];
            aql[j][1] = *(const uint32_t*)&qb2[(size_t)(g + 8) * HID_ + k0];
            aql[j][2] = *(const uint32_t*)&qb2[(size_t)g * HID_ + k0 + 8];
            aql[j][3] = *(const uint32_t*)&qb2[(size_t)(g + 8) * HID_ + k0 + 8];
        }
    }

    float o[8][4];
#pragma unroll
    for (int i = 0; i < 8; i++)
#pragma unroll
        for (int j = 0; j < 4; j++) o[i][j] = 0.f;
    float m0 = -INFINITY, m1 = -INFINITY, l0 = 0.f, l1 = 0.f;

    const int ntiles = 2 * qt + 2;

    auto issue = [&](int kt, int st) {
        uint32_t so = sb + (uint32_t)st * 4 * KVT * 2;
#pragma unroll
        for (int i = 0; i < 2; i++) {
            int idx = tid + i * 256;
            int r = idx >> 3, q = idx & 7;
            size_t go = ((size_t)(b * S_ + kt * 64 + r)) * NKVD + kvh * HD_ + q * 8;
            uint32_t off = (r * LDK + q * 8) * 2;
            cp16(so + off,               kh + go);
            cp16(so + KVT * 2 + off,     kl + go);
            cp16(so + 2 * KVT * 2 + off, vh + go);
            cp16(so + 3 * KVT * 2 + off, vl + go);
        }
        cp_commit();
    };

    issue(0, 0);
    if (ntiles > 1) issue(1, 1);

    for (int kt = 0; kt < ntiles; kt++) {
        if (kt + 1 < ntiles) cp_wait1(); else cp_wait0();
        __syncthreads();
        if (kt + 2 < ntiles) issue(kt + 2, (kt + 2) % FSTG);

        const uint32_t sg = sb + (uint32_t)(kt % FSTG) * 4 * KVT * 2;
        const uint32_t sKh_ = sg, sKl_ = sg + KVT * 2;
        const uint32_t sVh_ = sg + 2 * KVT * 2, sVl_ = sg + 3 * KVT * 2;

        const bool skip = (kt * 64) > (row_base + 15);
        if (!skip) {
            // --- S = scale * Q K^T ---
            float s[8][4];
#pragma unroll
            for (int i = 0; i < 8; i++)
#pragma unroll
                for (int j = 0; j < 4; j++) s[i][j] = 0.f;
#pragma unroll
            for (int j = 0; j < 4; j++) {
                const int kb = j * 16 + kq * 8;
#pragma unroll
                for (int kp = 0; kp < 4; kp++) {
                    uint32_t ad = ((kp * 16 + l8 + half * 8) * LDK + kb) * 2;
                    uint32_t th[4], tl[4];
                    ldsm4(th, sKh_ + ad);
                    ldsm4(tl, sKl_ + ad);
                    uint32_t be0[2] = {th[0], th[2]}, be1[2] = {th[1], th[3]};
                    uint32_t bl0[2] = {tl[0], tl[2]}, bl1[2] = {tl[1], tl[3]};
                    mma16816(s[2 * kp], aqh[j], be0);
                    mma16816(s[2 * kp], aqh[j], bl0);
                    mma16816(s[2 * kp], aql[j], be0);
                    mma16816(s[2 * kp + 1], aqh[j], be1);
                    mma16816(s[2 * kp + 1], aqh[j], bl1);
                    mma16816(s[2 * kp + 1], aql[j], be1);
                }
            }
            const int r0 = row_base + g, r1 = row_base + g + 8;
#pragma unroll
            for (int ni = 0; ni < 8; ni++) {
                int c0 = kt * 64 + ni * 8 + 2 * t;
                s[ni][0] *= SCALE; s[ni][1] *= SCALE; s[ni][2] *= SCALE; s[ni][3] *= SCALE;
                if ((kt * 64 + 63) > r0 || (kt * 64 + 63) > r1) {
                    if (c0 > r0)     s[ni][0] = -INFINITY;
                    if (c0 + 1 > r0) s[ni][1] = -INFINITY;
                    if (c0 > r1)     s[ni][2] = -INFINITY;
                    if (c0 + 1 > r1) s[ni][3] = -INFINITY;
                }
            }
            // --- softmax update ---
            float mx0 = -INFINITY, mx1 = -INFINITY;
#pragma unroll
            for (int ni = 0; ni < 8; ni++) {
                mx0 = fmaxf(mx0, fmaxf(s[ni][0], s[ni][1]));
                mx1 = fmaxf(mx1, fmaxf(s[ni][2], s[ni][3]));
            }
            mx0 = fmaxf(mx0, __shfl_xor_sync(0xffffffff, mx0, 1));
            mx0 = fmaxf(mx0, __shfl_xor_sync(0xffffffff, mx0, 2));
            mx1 = fmaxf(mx1, __shfl_xor_sync(0xffffffff, mx1, 1));
            mx1 = fmaxf(mx1, __shfl_xor_sync(0xffffffff, mx1, 2));

            float mn0 = fmaxf(m0, mx0), mn1 = fmaxf(m1, mx1);
            float f0 = __expf(m0 - mn0), f1 = __expf(m1 - mn1);
            m0 = mn0; m1 = mn1;

            float sum0 = 0.f, sum1 = 0.f;
#pragma unroll
            for (int ni = 0; ni < 8; ni++) {
                s[ni][0] = __expf(s[ni][0] - mn0);
                s[ni][1] = __expf(s[ni][1] - mn0);
                s[ni][2] = __expf(s[ni][2] - mn1);
                s[ni][3] = __expf(s[ni][3] - mn1);
                sum0 += s[ni][0] + s[ni][1];
                sum1 += s[ni][2] + s[ni][3];
            }
            sum0 += __shfl_xor_sync(0xffffffff, sum0, 1);
            sum0 += __shfl_xor_sync(0xffffffff, sum0, 2);
            sum1 += __shfl_xor_sync(0xffffffff, sum1, 1);
            sum1 += __shfl_xor_sync(0xffffffff, sum1, 2);
            l0 = l0 * f0 + sum0;
            l1 = l1 * f1 + sum1;

#pragma unroll
            for (int nd = 0; nd < 8; nd++) {
                o[nd][0] *= f0; o[nd][1] *= f0;
                o[nd][2] *= f1; o[nd][3] *= f1;
            }

            // --- repack P into A fragments (hi/lo) ---
            uint32_t pfh[4][4], pfl[4][4];
#pragma unroll
            for (int j = 0; j < 4; j++) {
                float p00 = s[2 * j][0],     p01 = s[2 * j][1];
                float p10 = s[2 * j][2],     p11 = s[2 * j][3];
                float p20 = s[2 * j + 1][0], p21 = s[2 * j + 1][1];
                float p30 = s[2 * j + 1][2], p31 = s[2 * j + 1][3];
                pfh[j][0] = pack_bf16(p00, p01);
                pfh[j][1] = pack_bf16(p10, p11);
                pfh[j][2] = pack_bf16(p20, p21);
                pfh[j][3] = pack_bf16(p30, p31);
                __nv_bfloat162* hp;
                hp = (__nv_bfloat162*)&pfh[j][0];
                pfl[j][0] = pack_bf16(p00 - __bfloat162float(hp->x), p01 - __bfloat162float(hp->y));
                hp = (__nv_bfloat162*)&pfh[j][1];
                pfl[j][1] = pack_bf16(p10 - __bfloat162float(hp->x), p11 - __bfloat162float(hp->y));
                hp = (__nv_bfloat162*)&pfh[j][2];
                pfl[j][2] = pack_bf16(p20 - __bfloat162float(hp->x), p21 - __bfloat162float(hp->y));
                hp = (__nv_bfloat162*)&pfh[j][3];
                pfl[j][3] = pack_bf16(p30 - __bfloat162float(hp->x), p31 - __bfloat162float(hp->y));
            }

            // --- O += P V (ldmatrix.trans on V, B-frags for 2 dim-tiles) ---
#pragma unroll
            for (int j = 0; j < 4; j++) {      // key chunk
#pragma unroll
                for (int dp = 0; dp < 4; dp++) {   // dim pair
                    uint32_t ad = ((j * 16 + kq * 8 + l8) * LDK + dp * 16 + half * 8) * 2;
                    uint32_t th[4], tl[4];
                    ldsm4t(th, sVh_ + ad);
                    ldsm4t(tl, sVl_ + ad);
                    uint32_t b0a[2] = {th[0], th[2]}, b1a[2] = {th[1], th[3]};
                    uint32_t b0b[2] = {tl[0], tl[2]}, b1b[2] = {tl[1], tl[3]};
                    mma16816(o[2 * dp], pfh[j], b0a);
                    mma16816(o[2 * dp], pfh[j], b0b);
                    mma16816(o[2 * dp], pfl[j], b0a);
                    mma16816(o[2 * dp + 1], pfh[j], b1a);
                    mma16816(o[2 * dp + 1], pfh[j], b1b);
                    mma16816(o[2 * dp + 1], pfl[j], b1a);
                }
            }
        }
    }

    // --- normalize and write bf16 hi/lo context ---
    float li0 = 1.0f / l0, li1 = 1.0f / l1;
    const size_t r0 = (size_t)(b * S_ + row_base + g) * HID_ + h * HD_;
    const size_t r1 = (size_t)(b * S_ + row_base + g + 8) * HID_ + h * HD_;
#pragma unroll
    for (int nd = 0; nd < 8; nd++) {
        int c = nd * 8 + 2 * t;
        float v0 = o[nd][0] * li0, v1 = o[nd][1] * li0;
        float v2 = o[nd][2] * li1, v3 = o[nd][3] * li1;
        uint32_t h01 = pack_bf16(v0, v1), h23 = pack_bf16(v2, v3);
        __nv_bfloat162* hp;
        hp = (__nv_bfloat162*)&h01;
        uint32_t l01 = pack_bf16(v0 - __bfloat162float(hp->x), v1 - __bfloat162float(hp->y));
        hp = (__nv_bfloat162*)&h23;
        uint32_t l23 = pack_bf16(v2 - __bfloat162float(hp->x), v3 - __bfloat162float(hp->y));
        *(uint32_t*)&ch[r0 + c] = h01;
        *(uint32_t*)&cl[r0 + c] = l01;
        *(uint32_t*)&ch[r1 + c] = h23;
        *(uint32_t*)&cl[r1 + c] = l23;
    }
}

// ---------------------------------------------------------------------------
// Launch
// ---------------------------------------------------------------------------
extern "C" void kernel_launch(void* const* d_in, const int* in_sizes, int n_in,
                              void* d_out, int out_size)
{
    const float* hidden = (const float*)d_in[0];
    const float* wq = (const float*)d_in[2];
    const float* wk = (const float*)d_in[3];
    const float* wv = (const float*)d_in[4];
    const float* wo = (const float*)d_in[5];
    float* out = (float*)d_out;

    float *qbuf, *kbuf, *vbuf;
    cudaGetSymbolAddress((void**)&qbuf, g_Q);
    cudaGetSymbolAddress((void**)&kbuf, g_K);
    cudaGetSymbolAddress((void**)&vbuf, g_V);

    __nv_bfloat16 *hh, *hl, *wqh, *wql, *wkh, *wkl, *wvh, *wvl, *woh, *wol;
    __nv_bfloat16 *qh, *ql, *kh, *kl, *vh, *vl, *ch, *cl;
    cudaGetSymbolAddress((void**)&hh, g_hh);   cudaGetSymbolAddress((void**)&hl, g_hl);
    cudaGetSymbolAddress((void**)&wqh, g_wqh); cudaGetSymbolAddress((void**)&wql, g_wql);
    cudaGetSymbolAddress((void**)&wkh, g_wkh); cudaGetSymbolAddress((void**)&wkl, g_wkl);
    cudaGetSymbolAddress((void**)&wvh, g_wvh); cudaGetSymbolAddress((void**)&wvl, g_wvl);
    cudaGetSymbolAddress((void**)&woh, g_woh); cudaGetSymbolAddress((void**)&wol, g_wol);
    cudaGetSymbolAddress((void**)&qh, g_qh);   cudaGetSymbolAddress((void**)&ql, g_ql);
    cudaGetSymbolAddress((void**)&kh, g_kh);   cudaGetSymbolAddress((void**)&kl, g_kl);
    cudaGetSymbolAddress((void**)&vh, g_vh);   cudaGetSymbolAddress((void**)&vl, g_vl);
    cudaGetSymbolAddress((void**)&ch, g_ch);   cudaGetSymbolAddress((void**)&cl, g_cl);

    const int GEMM_DYN = GSTG * 4 * TILE * 2;    // 122880 B
    const int FLASH_DYN = FSTG * 4 * KVT * 2;    // 110592 B
    cudaFuncSetAttribute(gemm_mma, cudaFuncAttributeMaxDynamicSharedMemorySize, GEMM_DYN);
    cudaFuncSetAttribute(flash_mma, cudaFuncAttributeMaxDynamicSharedMemorySize, FLASH_DYN);

    // Split inputs to bf16 hi/lo
    {
        int n1 = M_TOT * HID_;
        split_bf16<<<(n1 + 255) / 256, 256>>>(hidden, hh, hl, n1);
        int n2 = HID_ * HID_;
        split_bf16<<<(n2 + 255) / 256, 256>>>(wq, wqh, wql, n2);
        int n3 = NKVD * HID_;
        split_bf16<<<(n3 + 255) / 256, 256>>>(wk, wkh, wkl, n3);
        split_bf16<<<(n3 + 255) / 256, 256>>>(wv, wvh, wvl, n3);
        split_bf16<<<(n2 + 255) / 256, 256>>>(wo, woh, wol, n2);
    }

    rope_table_kernel<<<(S_ * 32) / 256, 256>>>();

    // Projections
    gemm_mma<<<dim3(HID_ / BN, M_TOT / BM), 512, GEMM_DYN>>>(hh, hl, wqh, wql, qbuf, M_TOT, HID_, HID_);
    gemm_mma<<<dim3(NKVD / BN, M_TOT / BM), 512, GEMM_DYN>>>(hh, hl, wkh, wkl, kbuf, M_TOT, NKVD, HID_);
    gemm_mma<<<dim3(NKVD / BN, M_TOT / BM), 512, GEMM_DYN>>>(hh, hl, wvh, wvl, vbuf, M_TOT, NKVD, HID_);

    // RoPE + split to bf16
    rope_split_kernel<<<(M_TOT * NH_ * 32) / 256, 256>>>(qbuf, qh, ql, NH_);
    rope_split_kernel<<<(M_TOT * NKV_ * 32) / 256, 256>>>(kbuf, kh, kl, NKV_);
    {
        int n3 = M_TOT * NKVD;
        split_bf16<<<(n3 + 255) / 256, 256>>>(vbuf, vh, vl, n3);
    }

    // Tensor-core flash attention (writes split context)
    flash_mma<<<dim3(S_ / 128, NH_, B_), 256, FLASH_DYN>>>(qh, ql, kh, kl, vh, vl, ch, cl);

    // O projection
    gemm_mma<<<dim3(HID_ / BN, M_TOT / BM), 512, GEMM_DYN>>>(ch, cl, woh, wol, out, M_TOT, HID_, HID_);
}

// round 7
// speedup vs baseline: 5.6435x; 1.0873x over previous
#include <cuda_runtime.h>
#include <cuda_bf16.h>
#include <cstdint>
#include <math.h>

// Problem constants
#define B_   2
#define S_   2048
#define HID_ 2048
#define NH_  32
#define NKV_ 8
#define HD_  64
#define GROUP_ 4
#define M_TOT (B_ * S_)          // 4096
#define NKVD (NKV_ * HD_)        // 512
#define NQKV (HID_ + 2 * NKVD)   // 3072

// ---------------------------------------------------------------------------
// Scratch (__device__ globals; no cudaMalloc allowed)
// ---------------------------------------------------------------------------
__device__ float g_QKV[(size_t)M_TOT * NQKV];     // fused projection output

__device__ __nv_bfloat16 g_hh[(size_t)M_TOT * HID_], g_hl[(size_t)M_TOT * HID_];
__device__ __nv_bfloat16 g_wch[(size_t)NQKV * HID_], g_wcl[(size_t)NQKV * HID_];  // wq|wk|wv
__device__ __nv_bfloat16 g_woh[(size_t)HID_ * HID_], g_wol[(size_t)HID_ * HID_];
__device__ __nv_bfloat16 g_qh[(size_t)M_TOT * HID_], g_ql[(size_t)M_TOT * HID_];
__device__ __nv_bfloat16 g_kh[(size_t)M_TOT * NKVD], g_kl[(size_t)M_TOT * NKVD];
__device__ __nv_bfloat16 g_vh[(size_t)M_TOT * NKVD], g_vl[(size_t)M_TOT * NKVD];
__device__ __nv_bfloat16 g_ch[(size_t)M_TOT * HID_], g_cl[(size_t)M_TOT * HID_];

__device__ float g_rsin[S_ * 32], g_rcos[S_ * 32];

// ---------------------------------------------------------------------------
// Helpers
// ---------------------------------------------------------------------------
__device__ __forceinline__ uint32_t smem_u32(const void* p) {
    uint32_t a;
    asm("{ .reg .u64 t; cvta.to.shared.u64 t, %1; cvt.u32.u64 %0, t; }" : "=r"(a) : "l"(p));
    return a;
}
__device__ __forceinline__ void cp16(uint32_t dst, const void* src) {
    asm volatile("cp.async.cg.shared.global [%0], [%1], 16;" :: "r"(dst), "l"(src));
}
__device__ __forceinline__ void cp_commit() { asm volatile("cp.async.commit_group;"); }
__device__ __forceinline__ void cp_wait1() { asm volatile("cp.async.wait_group 1;"); }
__device__ __forceinline__ void cp_wait0() { asm volatile("cp.async.wait_group 0;"); }
__device__ __forceinline__ void ldsm4(uint32_t* r, uint32_t addr) {
    asm volatile("ldmatrix.sync.aligned.m8n8.x4.shared.b16 {%0,%1,%2,%3}, [%4];"
        : "=r"(r[0]), "=r"(r[1]), "=r"(r[2]), "=r"(r[3]) : "r"(addr));
}
__device__ __forceinline__ void ldsm4t(uint32_t* r, uint32_t addr) {
    asm volatile("ldmatrix.sync.aligned.m8n8.x4.trans.shared.b16 {%0,%1,%2,%3}, [%4];"
        : "=r"(r[0]), "=r"(r[1]), "=r"(r[2]), "=r"(r[3]) : "r"(addr));
}
__device__ __forceinline__ void mma16816(float* c, const uint32_t* a, const uint32_t* b) {
    asm volatile(
        "mma.sync.aligned.m16n8k16.row.col.f32.bf16.bf16.f32 "
        "{%0,%1,%2,%3}, {%4,%5,%6,%7}, {%8,%9}, {%0,%1,%2,%3};"
        : "+f"(c[0]), "+f"(c[1]), "+f"(c[2]), "+f"(c[3])
        : "r"(a[0]), "r"(a[1]), "r"(a[2]), "r"(a[3]), "r"(b[0]), "r"(b[1]));
}
__device__ __forceinline__ uint32_t pack_bf16(float x, float y) {
    __nv_bfloat162 h = __floats2bfloat162_rn(x, y);
    return *(uint32_t*)&h;
}

// ---------------------------------------------------------------------------
// fp32 -> bf16 hi/lo split
// ---------------------------------------------------------------------------
__global__ void split_bf16(const float* __restrict__ x,
                           __nv_bfloat16* __restrict__ hi,
                           __nv_bfloat16* __restrict__ lo, int n) {
    int i = blockIdx.x * blockDim.x + threadIdx.x;
    if (i < n) {
        float v = x[i];
        __nv_bfloat16 h = __float2bfloat16(v);
        hi[i] = h;
        lo[i] = __float2bfloat16(v - __bfloat162float(h));
    }
}

// ---------------------------------------------------------------------------
// mma.sync bf16x3 GEMM. CTA tile 128x256x32, 512 thr (16 warps, warp 32x64).
// 3-stage cp.async pipeline, ldmatrix fragments. C[M,N] = A[M,K]*B[N,K]^T.
// ---------------------------------------------------------------------------
#define BM 128
#define BN 256
#define BK 32
#define LDSS 40
#define ATILE (BM * LDSS)                     // 5120 elems
#define BTILE (BN * LDSS)                     // 10240 elems
#define STG_EL (2 * ATILE + 2 * BTILE)        // 30720 elems / stage
#define GSTG 3

__global__ void __launch_bounds__(512, 1) gemm_mma(
    const __nv_bfloat16* __restrict__ Ah, const __nv_bfloat16* __restrict__ Al,
    const __nv_bfloat16* __restrict__ Bh, const __nv_bfloat16* __restrict__ Bl,
    float* __restrict__ C, int M, int N, int K)
{
    extern __shared__ __nv_bfloat16 dyn[];

    const int tid = threadIdx.x;
    const int warp = tid >> 5, lane = tid & 31;
    const int wm = (warp >> 2) * 32;        // 0..96
    const int wn = (warp & 3) * 64;         // 0..192
    const int g = lane >> 2, t = lane & 3;
    const int l8 = lane & 7, half = (lane >> 3) & 1, kq = lane >> 4;
    const int m0 = blockIdx.y * BM, n0 = blockIdx.x * BN;

    const uint32_t sb = smem_u32(dyn);
    const int arow = tid >> 2, aq = tid & 3;   // A: 512 slots

    float acc[2][8][4];
#pragma unroll
    for (int i = 0; i < 2; i++)
#pragma unroll
        for (int j = 0; j < 8; j++)
#pragma unroll
            for (int x = 0; x < 4; x++) acc[i][j][x] = 0.f;

    const int nch = K / BK;

    auto issue = [&](int kc, int st) {
        uint32_t so = sb + (uint32_t)st * STG_EL * 2;
        size_t ga = (size_t)(m0 + arow) * K + kc * BK + aq * 8;
        uint32_t aoff = (arow * LDSS + aq * 8) * 2;
        cp16(so + aoff,             Ah + ga);
        cp16(so + ATILE * 2 + aoff, Al + ga);
#pragma unroll
        for (int i = 0; i < 2; i++) {
            int idx = tid + i * 512;
            int brow = idx >> 2, bq = idx & 3;
            size_t gb = (size_t)(n0 + brow) * K + kc * BK + bq * 8;
            uint32_t boff = (brow * LDSS + bq * 8) * 2;
            cp16(so + 2 * ATILE * 2 + boff,               Bh + gb);
            cp16(so + (2 * ATILE + BTILE) * 2 + boff,     Bl + gb);
        }
        cp_commit();
    };

    issue(0, 0);
    if (nch > 1) issue(1, 1);

    for (int kc = 0; kc < nch; kc++) {
        if (kc + 1 < nch) cp_wait1(); else cp_wait0();
        __syncthreads();
        if (kc + 2 < nch) issue(kc + 2, (kc + 2) % GSTG);

        const uint32_t sa = sb + (uint32_t)(kc % GSTG) * STG_EL * 2;
        const uint32_t sAh_ = sa, sAl_ = sa + ATILE * 2;
        const uint32_t sBh_ = sa + 2 * ATILE * 2, sBl_ = sa + (2 * ATILE + BTILE) * 2;

#pragma unroll
        for (int ks = 0; ks < 2; ks++) {
            const int kb = ks * 16 + kq * 8;
            uint32_t afh[2][4], afl[2][4];
#pragma unroll
            for (int mi = 0; mi < 2; mi++) {
                uint32_t ad = ((wm + mi * 16 + l8 + half * 8) * LDSS + kb) * 2;
                ldsm4(afh[mi], sAh_ + ad);
                ldsm4(afl[mi], sAl_ + ad);
            }
#pragma unroll
            for (int p = 0; p < 4; p++) {
                uint32_t bd = ((wn + p * 16 + l8 + half * 8) * LDSS + kb) * 2;
                uint32_t th[4], tl[4];
                ldsm4(th, sBh_ + bd);
                ldsm4(tl, sBl_ + bd);
                uint32_t be0[2] = {th[0], th[2]}, be1[2] = {th[1], th[3]};
                uint32_t bl0[2] = {tl[0], tl[2]}, bl1[2] = {tl[1], tl[3]};
#pragma unroll
                for (int mi = 0; mi < 2; mi++) {
                    mma16816(acc[mi][2 * p],     afh[mi], be0);
                    mma16816(acc[mi][2 * p],     afh[mi], bl0);
                    mma16816(acc[mi][2 * p],     afl[mi], be0);
                    mma16816(acc[mi][2 * p + 1], afh[mi], be1);
                    mma16816(acc[mi][2 * p + 1], afh[mi], bl1);
                    mma16816(acc[mi][2 * p + 1], afl[mi], be1);
                }
            }
        }
    }

#pragma unroll
    for (int mi = 0; mi < 2; mi++) {
        int r = m0 + wm + mi * 16 + g;
#pragma unroll
        for (int ni = 0; ni < 8; ni++) {
            int c = n0 + wn + ni * 8 + 2 * t;
            *(float2*)&C[(size_t)r * N + c] = make_float2(acc[mi][ni][0], acc[mi][ni][1]);
            *(float2*)&C[(size_t)(r + 8) * N + c] = make_float2(acc[mi][ni][2], acc[mi][ni][3]);
        }
    }
}

// ---------------------------------------------------------------------------
// RoPE: table + apply-and-split (fp32 strided in, bf16 hi/lo packed out)
// ---------------------------------------------------------------------------
__global__ void rope_table_kernel() {
    int i = blockIdx.x * blockDim.x + threadIdx.x;
    int s = i >> 5, f = i & 31;
    double inv_freq = exp(-(double)f / 32.0 * log(10000.0));
    double sd, cd;
    sincos((double)s * inv_freq, &sd, &cd);
    g_rsin[i] = (float)sd;
    g_rcos[i] = (float)cd;
}
__global__ void rope_split_kernel(const float* __restrict__ X,
                                  __nv_bfloat16* __restrict__ Xh,
                                  __nv_bfloat16* __restrict__ Xl,
                                  int nheads, int src_off) {
    int idx = blockIdx.x * blockDim.x + threadIdx.x;
    int i = idx & 31;
    int bh = idx >> 5;
    int h = bh % nheads;
    int bs = bh / nheads;
    int s = bs & (S_ - 1);
    float c = g_rcos[s * 32 + i], sn = g_rsin[s * 32 + i];
    size_t sbase = (size_t)bs * NQKV + src_off + h * HD_;
    size_t dbase = (size_t)bs * nheads * HD_ + (size_t)h * HD_;
    float x1 = X[sbase + i], x2 = X[sbase + i + 32];
    float y1 = x1 * c - x2 * sn;
    float y2 = x2 * c + x1 * sn;
    __nv_bfloat16 h1 = __float2bfloat16(y1);
    __nv_bfloat16 h2 = __float2bfloat16(y2);
    Xh[dbase + i] = h1;
    Xh[dbase + i + 32] = h2;
    Xl[dbase + i] = __float2bfloat16(y1 - __bfloat162float(h1));
    Xl[dbase + i + 32] = __float2bfloat16(y2 - __bfloat162float(h2));
}
__global__ void split_v_kernel(const float* __restrict__ X,
                               __nv_bfloat16* __restrict__ hi,
                               __nv_bfloat16* __restrict__ lo) {
    int idx = blockIdx.x * blockDim.x + threadIdx.x;   // M_TOT*NKVD
    int row = idx >> 9, col = idx & 511;
    float v = X[(size_t)row * NQKV + HID_ + NKVD + col];
    __nv_bfloat16 h = __float2bfloat16(v);
    hi[idx] = h;
    lo[idx] = __float2bfloat16(v - __bfloat162float(h));
}

// ---------------------------------------------------------------------------
// Tensor-core flash attention (bf16x3, causal), 3-stage cp.async K/V pipeline,
// ldmatrix K-frags + ldmatrix.trans V-frags.
// grid=(S/128, NH, B), block=256 (8 warps). Warp w: q rows w*16..w*16+15.
// ---------------------------------------------------------------------------
#define LDK 72
#define KVT (64 * LDK)
#define FSTG 3

__global__ void __launch_bounds__(256, 1) flash_mma(
    const __nv_bfloat16* __restrict__ qh, const __nv_bfloat16* __restrict__ ql,
    const __nv_bfloat16* __restrict__ kh, const __nv_bfloat16* __restrict__ kl,
    const __nv_bfloat16* __restrict__ vh, const __nv_bfloat16* __restrict__ vl,
    __nv_bfloat16* __restrict__ ch, __nv_bfloat16* __restrict__ cl)
{
    extern __shared__ __nv_bfloat16 fdyn[];

    const int tid = threadIdx.x;
    const int w = tid >> 5, lane = tid & 31;
    const int g = lane >> 2, t = lane & 3;
    const int l8 = lane & 7, half = (lane >> 3) & 1, kq = lane >> 4;
    const int qt = blockIdx.x, h = blockIdx.y, b = blockIdx.z;
    const int kvh = h / GROUP_;
    const int row_base = qt * 128 + w * 16;
    const float SCALE = 0.125f;
    const uint32_t sb = smem_u32(fdyn);

    uint32_t aqh[4][4], aql[4][4];
    {
        const __nv_bfloat16* qb = qh + ((size_t)(b * S_ + row_base)) * HID_ + h * HD_;
        const __nv_bfloat16* qb2 = ql + ((size_t)(b * S_ + row_base)) * HID_ + h * HD_;
#pragma unroll
        for (int j = 0; j < 4; j++) {
            int k0 = j * 16 + 2 * t;
            aqh[j][0] = *(const uint32_t*)&qb[(size_t)g * HID_ + k0];
            aqh[j][1] = *(const uint32_t*)&qb[(size_t)(g + 8) * HID_ + k0];
            aqh[j][2] = *(const uint32_t*)&qb[(size_t)g * HID_ + k0 + 8];
            aqh[j][3] = *(const uint32_t*)&qb[(size_t)(g + 8) * HID_ + k0 + 8];
            aql[j][0] = *(const uint32_t*)&qb2[(size_t)g * HID_ + k0];
            aql[j][1] = *(const uint32_t*)&qb2[(size_t)(g + 8) * HID_ + k0];
            aql[j][2] = *(const uint32_t*)&qb2[(size_t)g * HID_ + k0 + 8];
            aql[j][3] = *(const uint32_t*)&qb2[(size_t)(g + 8) * HID_ + k0 + 8];
        }
    }

    float o[8][4];
#pragma unroll
    for (int i = 0; i < 8; i++)
#pragma unroll
        for (int j = 0; j < 4; j++) o[i][j] = 0.f;
    float m0 = -INFINITY, m1 = -INFINITY, l0 = 0.f, l1 = 0.f;

    const int ntiles = 2 * qt + 2;

    auto issue = [&](int kt, int st) {
        uint32_t so = sb + (uint32_t)st * 4 * KVT * 2;
#pragma unroll
        for (int i = 0; i < 2; i++) {
            int idx = tid + i * 256;
            int r = idx >> 3, q = idx & 7;
            size_t go = ((size_t)(b * S_ + kt * 64 + r)) * NKVD + kvh * HD_ + q * 8;
            uint32_t off = (r * LDK + q * 8) * 2;
            cp16(so + off,               kh + go);
            cp16(so + KVT * 2 + off,     kl + go);
            cp16(so + 2 * KVT * 2 + off, vh + go);
            cp16(so + 3 * KVT * 2 + off, vl + go);
        }
        cp_commit();
    };

    issue(0, 0);
    if (ntiles > 1) issue(1, 1);

    for (int kt = 0; kt < ntiles; kt++) {
        if (kt + 1 < ntiles) cp_wait1(); else cp_wait0();
        __syncthreads();
        if (kt + 2 < ntiles) issue(kt + 2, (kt + 2) % FSTG);

        const uint32_t sg = sb + (uint32_t)(kt % FSTG) * 4 * KVT * 2;
        const uint32_t sKh_ = sg, sKl_ = sg + KVT * 2;
        const uint32_t sVh_ = sg + 2 * KVT * 2, sVl_ = sg + 3 * KVT * 2;

        const bool skip = (kt * 64) > (row_base + 15);
        if (!skip) {
            float s[8][4];
#pragma unroll
            for (int i = 0; i < 8; i++)
#pragma unroll
                for (int j = 0; j < 4; j++) s[i][j] = 0.f;
#pragma unroll
            for (int j = 0; j < 4; j++) {
                const int kb = j * 16 + kq * 8;
#pragma unroll
                for (int kp = 0; kp < 4; kp++) {
                    uint32_t ad = ((kp * 16 + l8 + half * 8) * LDK + kb) * 2;
                    uint32_t th[4], tl[4];
                    ldsm4(th, sKh_ + ad);
                    ldsm4(tl, sKl_ + ad);
                    uint32_t be0[2] = {th[0], th[2]}, be1[2] = {th[1], th[3]};
                    uint32_t bl0[2] = {tl[0], tl[2]}, bl1[2] = {tl[1], tl[3]};
                    mma16816(s[2 * kp], aqh[j], be0);
                    mma16816(s[2 * kp], aqh[j], bl0);
                    mma16816(s[2 * kp], aql[j], be0);
                    mma16816(s[2 * kp + 1], aqh[j], be1);
                    mma16816(s[2 * kp + 1], aqh[j], bl1);
                    mma16816(s[2 * kp + 1], aql[j], be1);
                }
            }
            const int r0 = row_base + g, r1 = row_base + g + 8;
#pragma unroll
            for (int ni = 0; ni < 8; ni++) {
                int c0 = kt * 64 + ni * 8 + 2 * t;
                s[ni][0] *= SCALE; s[ni][1] *= SCALE; s[ni][2] *= SCALE; s[ni][3] *= SCALE;
                if ((kt * 64 + 63) > r0 || (kt * 64 + 63) > r1) {
                    if (c0 > r0)     s[ni][0] = -INFINITY;
                    if (c0 + 1 > r0) s[ni][1] = -INFINITY;
                    if (c0 > r1)     s[ni][2] = -INFINITY;
                    if (c0 + 1 > r1) s[ni][3] = -INFINITY;
                }
            }
            float mx0 = -INFINITY, mx1 = -INFINITY;
#pragma unroll
            for (int ni = 0; ni < 8; ni++) {
                mx0 = fmaxf(mx0, fmaxf(s[ni][0], s[ni][1]));
                mx1 = fmaxf(mx1, fmaxf(s[ni][2], s[ni][3]));
            }
            mx0 = fmaxf(mx0, __shfl_xor_sync(0xffffffff, mx0, 1));
            mx0 = fmaxf(mx0, __shfl_xor_sync(0xffffffff, mx0, 2));
            mx1 = fmaxf(mx1, __shfl_xor_sync(0xffffffff, mx1, 1));
            mx1 = fmaxf(mx1, __shfl_xor_sync(0xffffffff, mx1, 2));

            float mn0 = fmaxf(m0, mx0), mn1 = fmaxf(m1, mx1);
            float f0 = __expf(m0 - mn0), f1 = __expf(m1 - mn1);
            m0 = mn0; m1 = mn1;

            float sum0 = 0.f, sum1 = 0.f;
#pragma unroll
            for (int ni = 0; ni < 8; ni++) {
                s[ni][0] = __expf(s[ni][0] - mn0);
                s[ni][1] = __expf(s[ni][1] - mn0);
                s[ni][2] = __expf(s[ni][2] - mn1);
                s[ni][3] = __expf(s[ni][3] - mn1);
                sum0 += s[ni][0] + s[ni][1];
                sum1 += s[ni][2] + s[ni][3];
            }
            sum0 += __shfl_xor_sync(0xffffffff, sum0, 1);
            sum0 += __shfl_xor_sync(0xffffffff, sum0, 2);
            sum1 += __shfl_xor_sync(0xffffffff, sum1, 1);
            sum1 += __shfl_xor_sync(0xffffffff, sum1, 2);
            l0 = l0 * f0 + sum0;
            l1 = l1 * f1 + sum1;

#pragma unroll
            for (int nd = 0; nd < 8; nd++) {
                o[nd][0] *= f0; o[nd][1] *= f0;
                o[nd][2] *= f1; o[nd][3] *= f1;
            }

            uint32_t pfh[4][4], pfl[4][4];
#pragma unroll
            for (int j = 0; j < 4; j++) {
                float p00 = s[2 * j][0],     p01 = s[2 * j][1];
                float p10 = s[2 * j][2],     p11 = s[2 * j][3];
                float p20 = s[2 * j + 1][0], p21 = s[2 * j + 1][1];
                float p30 = s[2 * j + 1][2], p31 = s[2 * j + 1][3];
                pfh[j][0] = pack_bf16(p00, p01);
                pfh[j][1] = pack_bf16(p10, p11);
                pfh[j][2] = pack_bf16(p20, p21);
                pfh[j][3] = pack_bf16(p30, p31);
                __nv_bfloat162* hp;
                hp = (__nv_bfloat162*)&pfh[j][0];
                pfl[j][0] = pack_bf16(p00 - __bfloat162float(hp->x), p01 - __bfloat162float(hp->y));
                hp = (__nv_bfloat162*)&pfh[j][1];
                pfl[j][1] = pack_bf16(p10 - __bfloat162float(hp->x), p11 - __bfloat162float(hp->y));
                hp = (__nv_bfloat162*)&pfh[j][2];
                pfl[j][2] = pack_bf16(p20 - __bfloat162float(hp->x), p21 - __bfloat162float(hp->y));
                hp = (__nv_bfloat162*)&pfh[j][3];
                pfl[j][3] = pack_bf16(p30 - __bfloat162float(hp->x), p31 - __bfloat162float(hp->y));
            }

#pragma unroll
            for (int j = 0; j < 4; j++) {
#pragma unroll
                for (int dp = 0; dp < 4; dp++) {
                    uint32_t ad = ((j * 16 + kq * 8 + l8) * LDK + dp * 16 + half * 8) * 2;
                    uint32_t th[4], tl[4];
                    ldsm4t(th, sVh_ + ad);
                    ldsm4t(tl, sVl_ + ad);
                    uint32_t b0a[2] = {th[0], th[2]}, b1a[2] = {th[1], th[3]};
                    uint32_t b0b[2] = {tl[0], tl[2]}, b1b[2] = {tl[1], tl[3]};
                    mma16816(o[2 * dp], pfh[j], b0a);
                    mma16816(o[2 * dp], pfh[j], b0b);
                    mma16816(o[2 * dp], pfl[j], b0a);
                    mma16816(o[2 * dp + 1], pfh[j], b1a);
                    mma16816(o[2 * dp + 1], pfh[j], b1b);
                    mma16816(o[2 * dp + 1], pfl[j], b1a);
                }
            }
        }
    }

    float li0 = 1.0f / l0, li1 = 1.0f / l1;
    const size_t r0 = (size_t)(b * S_ + row_base + g) * HID_ + h * HD_;
    const size_t r1 = (size_t)(b * S_ + row_base + g + 8) * HID_ + h * HD_;
#pragma unroll
    for (int nd = 0; nd < 8; nd++) {
        int c = nd * 8 + 2 * t;
        float v0 = o[nd][0] * li0, v1 = o[nd][1] * li0;
        float v2 = o[nd][2] * li1, v3 = o[nd][3] * li1;
        uint32_t h01 = pack_bf16(v0, v1), h23 = pack_bf16(v2, v3);
        __nv_bfloat162* hp;
        hp = (__nv_bfloat162*)&h01;
        uint32_t l01 = pack_bf16(v0 - __bfloat162float(hp->x), v1 - __bfloat162float(hp->y));
        hp = (__nv_bfloat162*)&h23;
        uint32_t l23 = pack_bf16(v2 - __bfloat162float(hp->x), v3 - __bfloat162float(hp->y));
        *(uint32_t*)&ch[r0 + c] = h01;
        *(uint32_t*)&cl[r0 + c] = l01;
        *(uint32_t*)&ch[r1 + c] = h23;
        *(uint32_t*)&cl[r1 + c] = l23;
    }
}

// ---------------------------------------------------------------------------
// Launch
// ---------------------------------------------------------------------------
extern "C" void kernel_launch(void* const* d_in, const int* in_sizes, int n_in,
                              void* d_out, int out_size)
{
    const float* hidden = (const float*)d_in[0];
    const float* wq = (const float*)d_in[2];
    const float* wk = (const float*)d_in[3];
    const float* wv = (const float*)d_in[4];
    const float* wo = (const float*)d_in[5];
    float* out = (float*)d_out;

    float* qkv;
    cudaGetSymbolAddress((void**)&qkv, g_QKV);

    __nv_bfloat16 *hh, *hl, *wch, *wcl, *woh, *wol;
    __nv_bfloat16 *qh, *ql, *kh, *kl, *vh, *vl, *ch, *cl;
    cudaGetSymbolAddress((void**)&hh, g_hh);   cudaGetSymbolAddress((void**)&hl, g_hl);
    cudaGetSymbolAddress((void**)&wch, g_wch); cudaGetSymbolAddress((void**)&wcl, g_wcl);
    cudaGetSymbolAddress((void**)&woh, g_woh); cudaGetSymbolAddress((void**)&wol, g_wol);
    cudaGetSymbolAddress((void**)&qh, g_qh);   cudaGetSymbolAddress((void**)&ql, g_ql);
    cudaGetSymbolAddress((void**)&kh, g_kh);   cudaGetSymbolAddress((void**)&kl, g_kl);
    cudaGetSymbolAddress((void**)&vh, g_vh);   cudaGetSymbolAddress((void**)&vl, g_vl);
    cudaGetSymbolAddress((void**)&ch, g_ch);   cudaGetSymbolAddress((void**)&cl, g_cl);

    const int GEMM_DYN = GSTG * STG_EL * 2;      // 184320 B
    const int FLASH_DYN = FSTG * 4 * KVT * 2;    // 110592 B
    cudaFuncSetAttribute(gemm_mma, cudaFuncAttributeMaxDynamicSharedMemorySize, GEMM_DYN);
    cudaFuncSetAttribute(flash_mma, cudaFuncAttributeMaxDynamicSharedMemorySize, FLASH_DYN);

    // Split inputs to bf16 hi/lo (QKV weights concatenated)
    {
        int n1 = M_TOT * HID_;
        split_bf16<<<(n1 + 255) / 256, 256>>>(hidden, hh, hl, n1);
        int n2 = HID_ * HID_;
        split_bf16<<<(n2 + 255) / 256, 256>>>(wq, wch, wcl, n2);
        int n3 = NKVD * HID_;
        split_bf16<<<(n3 + 255) / 256, 256>>>(wk, wch + (size_t)HID_ * HID_, wcl + (size_t)HID_ * HID_, n3);
        split_bf16<<<(n3 + 255) / 256, 256>>>(wv, wch + (size_t)(HID_ + NKVD) * HID_, wcl + (size_t)(HID_ + NKVD) * HID_, n3);
        split_bf16<<<(n2 + 255) / 256, 256>>>(wo, woh, wol, n2);
    }

    rope_table_kernel<<<(S_ * 32) / 256, 256>>>();

    // Fused QKV projection
    gemm_mma<<<dim3(NQKV / BN, M_TOT / BM), 512, GEMM_DYN>>>(hh, hl, wch, wcl, qkv, M_TOT, NQKV, HID_);

    // RoPE + split to bf16
    rope_split_kernel<<<(M_TOT * NH_ * 32) / 256, 256>>>(qkv, qh, ql, NH_, 0);
    rope_split_kernel<<<(M_TOT * NKV_ * 32) / 256, 256>>>(qkv, kh, kl, NKV_, HID_);
    split_v_kernel<<<(M_TOT * NKVD) / 256, 256>>>(qkv, vh, vl);

    // Tensor-core flash attention (writes split context)
    flash_mma<<<dim3(S_ / 128, NH_, B_), 256, FLASH_DYN>>>(qh, ql, kh, kl, vh, vl, ch, cl);

    // O projection
    gemm_mma<<<dim3(HID_ / BN, M_TOT / BM), 512, GEMM_DYN>>>(ch, cl, woh, wol, out, M_TOT, HID_, HID_);
}